// round 12
// baseline (speedup 1.0000x reference)
#include <cuda_runtime.h>
#include <cuda_pipeline.h>
#include <math.h>
#include <stdint.h>

#define HH 96
#define WW 96
#define HW 9216
#define BATCH 4
#define PSTRIDE 9984      // padded-NHWC pixels per batch image
#define PBASE 128         // front guard (>= 99)
#define NTILE 76          // 76 tiles of 128 padded pixels cover 98*98=9604

typedef unsigned long long ull;

// ---------------- scratch (static device globals; zero-initialized) ----------------
__device__ float g_ha_hi[BATCH * PSTRIDE * 64];
__device__ float g_ha_lo[BATCH * PSTRIDE * 64];
__device__ float g_hb_hi[BATCH * PSTRIDE * 64];
__device__ float g_hb_lo[BATCH * PSTRIDE * 64];
__device__ float g_off[BATCH * 288 * HW];
__device__ float g_mask[BATCH * 144 * HW];
__device__ float g_xt[BATCH * HW * 128];
__device__ float g_wd[1152 * 64];
__device__ float g_w1hi[9 * 64 * 64],  g_w1lo[9 * 64 * 64];
__device__ float g_w2hi[9 * 64 * 64],  g_w2lo[9 * 64 * 64];
__device__ float g_w3hi[9 * 448 * 64], g_w3lo[9 * 448 * 64];   // rows 432..447 stay zero

// ---------------- packed f32x2 helpers ----------------
__device__ __forceinline__ void fma2(ull& d, ull a, ull b) {
    asm("fma.rn.f32x2 %0, %1, %2, %0;" : "+l"(d) : "l"(a), "l"(b));
}
__device__ __forceinline__ ull pack2(float lo, float hi) {
    ull r; asm("mov.b64 %0, {%1, %2};" : "=l"(r) : "f"(lo), "f"(hi)); return r;
}
__device__ __forceinline__ void unpack2(ull p, float& lo, float& hi) {
    asm("mov.b64 {%0, %1}, %2;" : "=f"(lo), "=f"(hi) : "l"(p));
}
__device__ __forceinline__ ull midpair(ull a, ull b) { return (a >> 32) | (b << 32); }

// ---------------- tf32 split ----------------
__device__ __forceinline__ void tsplit(float v, float& h, float& l) {
    uint32_t hb; asm("cvt.rna.tf32.f32 %0, %1;" : "=r"(hb) : "f"(v));
    h = __uint_as_float(hb);
    float r = v - h;
    uint32_t lb; asm("cvt.rna.tf32.f32 %0, %1;" : "=r"(lb) : "f"(r));
    l = __uint_as_float(lb);
}

// ---------------- warp mma m16n8k8 tf32 ----------------
__device__ __forceinline__ void mma8(float* c, const uint32_t* a, const uint32_t* b) {
    asm volatile(
        "mma.sync.aligned.m16n8k8.row.col.f32.tf32.tf32.f32 "
        "{%0,%1,%2,%3}, {%4,%5,%6,%7}, {%8,%9}, {%0,%1,%2,%3};"
        : "+f"(c[0]), "+f"(c[1]), "+f"(c[2]), "+f"(c[3])
        : "r"(a[0]), "r"(a[1]), "r"(a[2]), "r"(a[3]), "r"(b[0]), "r"(b[1]));
}

// ---------------- transpose x: NCHW -> N(HW)C ----------------
__global__ void transpose_x_kernel(const float* __restrict__ x, float* __restrict__ xt) {
    __shared__ float t[32][33];
    int b = blockIdx.z, y = blockIdx.y;
    int c0 = (blockIdx.x & 3) * 32;
    int w0 = (blockIdx.x >> 2) * 32;
    int tx = threadIdx.x, ty = threadIdx.y;
#pragma unroll
    for (int j = 0; j < 4; j++) {
        int c = c0 + ty + j * 8;
        t[ty + j * 8][tx] = x[((b * 128 + c) * HH + y) * WW + w0 + tx];
    }
    __syncthreads();
#pragma unroll
    for (int j = 0; j < 4; j++) {
        int w = w0 + ty + j * 8;
        xt[((size_t)b * HW + (size_t)y * WW + w) * 128 + c0 + tx] = t[tx][ty + j * 8];
    }
}

// ---------------- deform-weight transpose ----------------
__global__ void prep_wd_kernel(const float* __restrict__ wgt, float* __restrict__ wd) {
    int i = blockIdx.x * 256 + threadIdx.x;
    int kk = i >> 6, o = i & 63;
    int g = kk / 72, r = kk - g * 72;
    int k = r >> 3, c = r & 7;
    wd[i] = wgt[(o * 128 + g * 8 + c) * 9 + k];
}

// ---------------- conv weight hi/lo split -> [tap][oc(OCP)][64ch] ----------------
__global__ void prep_wsplit_kernel(const float* __restrict__ src, float* __restrict__ hi,
                                   float* __restrict__ lo, int OC, int OCP) {
    int i = blockIdx.x * 256 + threadIdx.x;
    int n = 9 * OCP * 64;
    if (i >= n) return;
    int c = i & 63;
    int rest = i >> 6;
    int oc = rest % OCP;
    int tap = rest / OCP;
    if (oc >= OC) return;
    float w = src[((oc * 64 + c) * 3 + tap / 3) * 3 + (tap % 3)];
    float h, l;
    tsplit(w, h, l);
    hi[i] = h;
    lo[i] = l;
}

// ---------------- conv0: scalar f32x2 (CIN=196 concat) -> padded NHWC hi/lo ----------------
#define SROW 104
__global__ __launch_bounds__(96) void conv0_kernel(
    const float* __restrict__ extra,
    const float* __restrict__ flow1,
    const float* __restrict__ flow2,
    const float* __restrict__ wgt,
    const float* __restrict__ bias,
    float* __restrict__ outhi,
    float* __restrict__ outlo)
{
    const int CIN = 196;
    __shared__ float s_in[3][4][10][SROW];
    __shared__ float2 s_w2[3][144];

    const int b = blockIdx.z;
    const int oc0 = blockIdx.y * 4;
    const int gy0 = blockIdx.x * 8;
    const int tid = threadIdx.x;
    const int tx = tid % 48;
    const int ty = tid / 48;
    const int nsteps = CIN / 4;

    const float4 z4 = make_float4(0.f, 0.f, 0.f, 0.f);
    for (int i = tid; i < 240; i += 96) {
        int bi = i / 80, rem = i % 80;
        int ck = rem / 20, rem2 = rem % 20;
        int r = rem2 >> 1, side = rem2 & 1;
        *(float4*)&s_in[bi][ck][r][side ? 100 : 0] = z4;
    }
    if (gy0 == 0 || gy0 == 88) {
        int rr = (gy0 == 0) ? 0 : 9;
        for (int i = tid; i < 312; i += 96) {
            int bi = i / 104, rem = i % 104;
            int ck = rem / 26, q = rem % 26;
            ((float4*)&s_in[bi][ck][rr][0])[q] = z4;
        }
    }

    int soff[10], doff[10];
    unsigned vmask = 0;
#pragma unroll
    for (int i = 0; i < 10; i++) {
        int t = tid + 96 * i;
        int q = t % 24, rc = t / 24;
        int ck = rc / 10, rr = rc - ck * 10;
        int gy = gy0 + rr - 1;
        soff[i] = ck * HW + gy * WW + 4 * q;
        doff[i] = rc * SROW + 4 + 4 * q;
        if ((unsigned)gy < (unsigned)HH) vmask |= 1u << i;
    }

    const int t0 = tid, t1 = tid + 96;
    const int o_0 = t0 / 36, ck_0 = (t0 % 36) / 9, k_0 = t0 % 9;
    const int o_1 = t1 / 36, ck_1 = (t1 % 36) / 9, k_1 = t1 % 9;
    const int wi0 = ((oc0 + o_0) * CIN + ck_0) * 9 + k_0;
    const int wi1 = ((oc0 + o_1) * CIN + ck_1) * 9 + k_1;

#define C0_STAGE(BI, C0)                                                                 \
    do {                                                                                 \
        float* db = &s_in[BI][0][0][0];                                                  \
        if ((C0) < 192) {                                                                \
            const float* base = extra + (size_t)(b * 192 + (C0)) * HW;                   \
            _Pragma("unroll")                                                            \
            for (int i = 0; i < 10; i++)                                                 \
                if ((vmask >> i) & 1)                                                    \
                    __pipeline_memcpy_async(db + doff[i], base + soff[i], 16);           \
        } else {                                                                         \
            _Pragma("unroll")                                                            \
            for (int i = 0; i < 10; i++) {                                               \
                if ((vmask >> i) & 1) {                                                  \
                    int t = tid + 96 * i;                                                \
                    int q = t % 24, rc = t / 24;                                         \
                    int ck = rc / 10, rr = rc - ck * 10;                                 \
                    int gy = gy0 + rr - 1;                                               \
                    const float* src = ((ck < 2) ? flow1 : flow2)                        \
                                       + (size_t)(b * 2 + (ck & 1)) * HW;                \
                    __pipeline_memcpy_async(db + doff[i], src + gy * WW + 4 * q, 16);    \
                }                                                                        \
            }                                                                            \
        }                                                                                \
    } while (0)

#define C0_STAGE_W(BI, C0)                                                               \
    do {                                                                                 \
        float w = wgt[wi0 + (C0) * 9];                                                   \
        s_w2[BI][t0] = make_float2(w, w);                                                \
        if (t1 < 144) {                                                                  \
            float w2v = wgt[wi1 + (C0) * 9];                                             \
            s_w2[BI][t1] = make_float2(w2v, w2v);                                        \
        }                                                                                \
    } while (0)

    C0_STAGE(0, 0);
    __pipeline_commit();
    C0_STAGE_W(0, 0);

    ull acc[4][4];
#pragma unroll
    for (int o = 0; o < 4; o++)
#pragma unroll
        for (int r = 0; r < 4; r++) acc[o][r] = 0ULL;

    int cur = 0;
    for (int s = 0; s < nsteps; s++) {
        int nxt = (cur == 2) ? 0 : cur + 1;
        if (s + 1 < nsteps) {
            const int c0n = (s + 1) * 4;
            C0_STAGE(nxt, c0n);
            __pipeline_commit();
            C0_STAGE_W(nxt, c0n);
            __pipeline_wait_prior(1);
        } else {
            __pipeline_wait_prior(0);
        }
        __syncthreads();

#pragma unroll
        for (int ck = 0; ck < 4; ck++) {
            ull P[6][3];
#pragma unroll
            for (int iy = 0; iy < 6; iy++) {
                const float* rp = &s_in[cur][ck][ty * 4 + iy][2 + 2 * tx];
                ull a = *(const ull*)rp;
                ull bb = *(const ull*)(rp + 2);
                ull c = *(const ull*)(rp + 4);
                P[iy][0] = midpair(a, bb);
                P[iy][1] = bb;
                P[iy][2] = midpair(bb, c);
            }
#pragma unroll
            for (int o = 0; o < 4; o++) {
                const float2* wrow = &s_w2[cur][o * 36 + ck * 9];
#pragma unroll
                for (int ky = 0; ky < 3; ky++)
#pragma unroll
                    for (int kx = 0; kx < 3; kx++) {
                        ull w2 = *(const ull*)&wrow[ky * 3 + kx];
#pragma unroll
                        for (int r = 0; r < 4; r++)
                            fma2(acc[o][r], P[r + ky][kx], w2);
                    }
            }
        }
        cur = nxt;
    }

#pragma unroll
    for (int o = 0; o < 4; o++) {
        int oc = oc0 + o;
        float bv = bias[oc];
#pragma unroll
        for (int rr = 0; rr < 4; rr++) {
            int gy = gy0 + ty * 4 + rr;
            int gx = 2 * tx;
            float v0, v1;
            unpack2(acc[o][rr], v0, v1);
            v0 += bv; v1 += bv;
            v0 = (v0 >= 0.f) ? v0 : 0.1f * v0;
            v1 = (v1 >= 0.f) ? v1 : 0.1f * v1;
            float h0, l0, h1, l1;
            tsplit(v0, h0, l0);
            tsplit(v1, h1, l1);
            size_t pb = ((size_t)b * PSTRIDE + PBASE + (gy + 1) * 98 + (gx + 1)) * 64 + oc;
            outhi[pb] = h0;      outlo[pb] = l0;
            outhi[pb + 64] = h1; outlo[pb + 64] = l1;
        }
    }
#undef C0_STAGE
#undef C0_STAGE_W
}

// ---------------- tensor conv via warp mma: 9-tap split-TF32 GEMM ----------------
// block 128 (4 warps); tile 128 px x 64 oc; warp = 32 px x 64 oc.
// smem: A window 326 rows x 68 floats (hi+lo) resident; B 64x68 (hi+lo) per tap.
#define APAD 68
#define ABYTES (326 * APAD * 4)          // 88672
#define OFF_AL ABYTES
#define OFF_BH (2 * ABYTES)              // 177344
#define OFF_BL (2 * ABYTES + 64 * APAD * 4)  // 194752
#define TCM_SMEM (OFF_BL + 64 * APAD * 4)    // 212160

template <int EPI, int OCP>
__global__ __launch_bounds__(128) void tconv_kernel(
    const float* __restrict__ inhi, const float* __restrict__ inlo,
    const float* __restrict__ wbhi, const float* __restrict__ wblo,
    const float* __restrict__ bias,
    float* __restrict__ outhi, float* __restrict__ outlo,
    float* __restrict__ offb, float* __restrict__ maskb,
    const float* __restrict__ flow1, const float* __restrict__ flow2)
{
    extern __shared__ __align__(16) char smem[];
    float* Ah = (float*)smem;
    float* Al = (float*)(smem + OFF_AL);
    float* Bh = (float*)(smem + OFF_BH);
    float* Bl = (float*)(smem + OFF_BL);

    const int tid = threadIdx.x;
    const int wid = tid >> 5, lane = tid & 31;
    const int gid = lane >> 2, tig = lane & 3;
    const int b = blockIdx.z, occ = blockIdx.y;
    const int p0 = blockIdx.x * 128;
    const size_t bb = (size_t)b * PSTRIDE + PBASE;

    // ---- stage A window rows [p0-99, p0+227) : 326 rows x 16 chunks x {hi,lo} ----
    {
        const char* sa0 = (const char*)inhi;
        const char* sa1 = (const char*)inlo;
        const size_t rowbase = bb + p0 - 99;
#pragma unroll 1
        for (int i = 0; i < 82; i++) {
            int cc = tid + 128 * i;
            if (cc >= 10432) break;
            int h = cc / 5216, rem = cc - h * 5216;
            int r = rem >> 4, q = rem & 15;
            float* dst = (h ? Al : Ah) + r * APAD + q * 4;
            const char* src = (h ? sa1 : sa0) + (rowbase + r) * 256 + q * 16;
            __pipeline_memcpy_async(dst, src, 16);
        }
        __pipeline_commit();
    }

    float acc[2][8][4];
#pragma unroll
    for (int mt = 0; mt < 2; mt++)
#pragma unroll
        for (int nt = 0; nt < 8; nt++)
#pragma unroll
            for (int e = 0; e < 4; e++) acc[mt][nt][e] = 0.f;

    for (int tap = 0; tap < 9; tap++) {
        __syncthreads();   // previous tap's B reads finished
        // ---- stage B for this tap: 64 rows x 16 chunks x {hi,lo} ----
        {
            const char* sb0 = (const char*)wbhi;
            const char* sb1 = (const char*)wblo;
            const size_t brow = (size_t)tap * OCP + occ * 64;
#pragma unroll
            for (int i = 0; i < 16; i++) {
                int cc = tid + 128 * i;           // 0..2047
                int h = cc >> 10, rem = cc & 1023;
                int r = rem >> 4, q = rem & 15;
                float* dst = (h ? Bl : Bh) + r * APAD + q * 4;
                const char* src = (h ? sb1 : sb0) + (brow + r) * 256 + q * 16;
                __pipeline_memcpy_async(dst, src, 16);
            }
            __pipeline_commit();
        }
        __pipeline_wait_prior(0);
        __syncthreads();

        const int shift = (tap / 3 - 1) * 98 + (tap % 3) - 1;
        const int abase0 = (wid * 32 + gid + 99 + shift) * APAD + tig;

#pragma unroll
        for (int ks = 0; ks < 8; ks++) {
            const int k = ks * 8;
            uint32_t ahf[2][4], alf[2][4], bhf[8][2], blf[8][2];
#pragma unroll
            for (int mt = 0; mt < 2; mt++) {
                int base = abase0 + mt * 16 * APAD + k;
                ahf[mt][0] = __float_as_uint(Ah[base]);
                ahf[mt][1] = __float_as_uint(Ah[base + 8 * APAD]);
                ahf[mt][2] = __float_as_uint(Ah[base + 4]);
                ahf[mt][3] = __float_as_uint(Ah[base + 8 * APAD + 4]);
                alf[mt][0] = __float_as_uint(Al[base]);
                alf[mt][1] = __float_as_uint(Al[base + 8 * APAD]);
                alf[mt][2] = __float_as_uint(Al[base + 4]);
                alf[mt][3] = __float_as_uint(Al[base + 8 * APAD + 4]);
            }
#pragma unroll
            for (int nt = 0; nt < 8; nt++) {
                int bbase = (nt * 8 + gid) * APAD + k + tig;
                bhf[nt][0] = __float_as_uint(Bh[bbase]);
                bhf[nt][1] = __float_as_uint(Bh[bbase + 4]);
                blf[nt][0] = __float_as_uint(Bl[bbase]);
                blf[nt][1] = __float_as_uint(Bl[bbase + 4]);
            }
#pragma unroll
            for (int mt = 0; mt < 2; mt++)
#pragma unroll
                for (int nt = 0; nt < 8; nt++) {
                    mma8(acc[mt][nt], ahf[mt], bhf[nt]);
                    mma8(acc[mt][nt], ahf[mt], blf[nt]);
                    mma8(acc[mt][nt], alf[mt], bhf[nt]);
                }
        }
    }

    // ---- epilogue ----
#pragma unroll
    for (int mt = 0; mt < 2; mt++) {
#pragma unroll
        for (int half = 0; half < 2; half++) {
            int pp = p0 + wid * 32 + mt * 16 + gid + half * 8;
            int r98 = pp / 98, c98 = pp - r98 * 98;
            bool valid = (r98 >= 1) && (r98 <= 96) && (c98 >= 1) && (c98 <= 96);
            if (!valid) continue;
            if (EPI == 0) {
                size_t ob = (bb + pp) * 64;
#pragma unroll
                for (int nt = 0; nt < 8; nt++) {
                    int oc = nt * 8 + tig * 2;
                    float v0 = acc[mt][nt][half * 2 + 0] + __ldg(&bias[oc]);
                    float v1 = acc[mt][nt][half * 2 + 1] + __ldg(&bias[oc + 1]);
                    v0 = (v0 >= 0.f) ? v0 : 0.1f * v0;
                    v1 = (v1 >= 0.f) ? v1 : 0.1f * v1;
                    float h0, l0, h1, l1;
                    tsplit(v0, h0, l0);
                    tsplit(v1, h1, l1);
                    *(float2*)&outhi[ob + oc] = make_float2(h0, h1);
                    *(float2*)&outlo[ob + oc] = make_float2(l0, l1);
                }
            } else {
                int y = r98 - 1, x = c98 - 1;
                int pix = y * WW + x;
                float f1a = __ldg(&flow1[(size_t)(b * 2 + 0) * HW + pix]);
                float f1b = __ldg(&flow1[(size_t)(b * 2 + 1) * HW + pix]);
                float f2a = __ldg(&flow2[(size_t)(b * 2 + 0) * HW + pix]);
                float f2b = __ldg(&flow2[(size_t)(b * 2 + 1) * HW + pix]);
#pragma unroll
                for (int nt = 0; nt < 8; nt++) {
#pragma unroll
                    for (int e = 0; e < 2; e++) {
                        int oc = occ * 64 + nt * 8 + tig * 2 + e;
                        if (oc >= 432) continue;
                        float v = acc[mt][nt][half * 2 + e] + __ldg(&bias[oc]);
                        if (oc < 288) {
                            int par = 1 - (oc & 1);
                            float f = (oc < 144) ? (par ? f1b : f1a) : (par ? f2b : f2a);
                            offb[((size_t)b * 288 + oc) * HW + pix] = 10.f * tanhf(v) + f;
                        } else {
                            maskb[((size_t)b * 144 + (oc - 288)) * HW + pix] =
                                1.f / (1.f + expf(-v));
                        }
                    }
                }
            }
        }
    }
}

// ---------------- deformable conv (unchanged) ----------------
#define SSTRIDE 1156

__global__ void deform_kernel(
    const float* __restrict__ xt,
    const float* __restrict__ off,
    const float* __restrict__ msk,
    const float* __restrict__ wd,
    const float* __restrict__ bias,
    float* __restrict__ out)
{
    extern __shared__ float s_sm[];
    int b = blockIdx.z;
    int h = blockIdx.y;
    int w0 = blockIdx.x * 16;
    int tid = threadIdx.x;
    {
        int px = tid & 15;
        int ww = w0 + px;
        int pospix = h * WW + ww;
        const float* offb = off + (size_t)b * 288 * HW + pospix;
        const float* mskb = msk + (size_t)b * 144 * HW + pospix;
        const float* xb = xt + (size_t)b * HW * 128;
#pragma unroll 1
        for (int it = 0; it < 9; it++) {
            int gk = (tid >> 4) + it * 16;
            int g = gk / 9, k = gk - g * 9;
            int ky = k / 3, kx = k - ky * 3;
            int oc = g * 18 + k * 2;
            float dy = offb[(size_t)oc * HW];
            float dx = offb[(size_t)(oc + 1) * HW];
            float m = mskb[(size_t)gk * HW];
            float py = dy + (float)(ky + h - 1);
            float pxx = dx + (float)(kx + ww - 1);
            float fy0 = floorf(py), fx0 = floorf(pxx);
            float wy1 = py - fy0, wx1 = pxx - fx0;
            int iy0 = (int)fy0, ix0 = (int)fx0;
            float a[8];
#pragma unroll
            for (int i = 0; i < 8; i++) a[i] = 0.f;
#pragma unroll
            for (int dyc = 0; dyc < 2; dyc++) {
#pragma unroll
                for (int dxc = 0; dxc < 2; dxc++) {
                    int yy = iy0 + dyc, xx = ix0 + dxc;
                    if ((unsigned)yy < HH && (unsigned)xx < WW) {
                        float wc = (dyc ? wy1 : 1.f - wy1) * (dxc ? wx1 : 1.f - wx1);
                        const float4* p = (const float4*)(xb + ((size_t)yy * WW + xx) * 128 + g * 8);
                        float4 v0 = p[0], v1 = p[1];
                        a[0] += wc * v0.x; a[1] += wc * v0.y; a[2] += wc * v0.z; a[3] += wc * v0.w;
                        a[4] += wc * v1.x; a[5] += wc * v1.y; a[6] += wc * v1.z; a[7] += wc * v1.w;
                    }
                }
            }
            float* sp = s_sm + px * SSTRIDE + g * 72 + k * 8;
            ((float4*)sp)[0] = make_float4(a[0] * m, a[1] * m, a[2] * m, a[3] * m);
            ((float4*)sp)[1] = make_float4(a[4] * m, a[5] * m, a[6] * m, a[7] * m);
        }
    }
    __syncthreads();
    {
        int og = tid & 15;
        int p2 = tid >> 4;
        const ulonglong2* wdv = (const ulonglong2*)wd;
        const float4* sr4 = (const float4*)(s_sm + p2 * SSTRIDE);
        float4 bbv = ((const float4*)bias)[og];
        ull a01 = pack2(bbv.x, bbv.y);
        ull a23 = pack2(bbv.z, bbv.w);
#pragma unroll 2
        for (int kk4 = 0; kk4 < 288; kk4++) {
            float4 sv = sr4[kk4];
            { ull ss = pack2(sv.x, sv.x); ulonglong2 wv = wdv[(kk4 * 4 + 0) * 16 + og];
              fma2(a01, wv.x, ss); fma2(a23, wv.y, ss); }
            { ull ss = pack2(sv.y, sv.y); ulonglong2 wv = wdv[(kk4 * 4 + 1) * 16 + og];
              fma2(a01, wv.x, ss); fma2(a23, wv.y, ss); }
            { ull ss = pack2(sv.z, sv.z); ulonglong2 wv = wdv[(kk4 * 4 + 2) * 16 + og];
              fma2(a01, wv.x, ss); fma2(a23, wv.y, ss); }
            { ull ss = pack2(sv.w, sv.w); ulonglong2 wv = wdv[(kk4 * 4 + 3) * 16 + og];
              fma2(a01, wv.x, ss); fma2(a23, wv.y, ss); }
        }
        float r0, r1, r2, r3;
        unpack2(a01, r0, r1);
        unpack2(a23, r2, r3);
        int oc = og * 4;
        size_t ob = (size_t)b * 64 * HW + (size_t)h * WW + w0 + p2;
        out[ob + (size_t)(oc + 0) * HW] = r0;
        out[ob + (size_t)(oc + 1) * HW] = r1;
        out[ob + (size_t)(oc + 2) * HW] = r2;
        out[ob + (size_t)(oc + 3) * HW] = r3;
    }
}

// ---------------- launch ----------------
extern "C" void kernel_launch(void* const* d_in, const int* in_sizes, int n_in,
                              void* d_out, int out_size)
{
    const float* x      = (const float*)d_in[0];
    const float* extra  = (const float*)d_in[1];
    const float* flow1  = (const float*)d_in[2];
    const float* flow2  = (const float*)d_in[3];
    const float* weight = (const float*)d_in[4];
    const float* bias   = (const float*)d_in[5];
    const float* ow0    = (const float*)d_in[6];
    const float* ob0    = (const float*)d_in[7];
    const float* ow1    = (const float*)d_in[8];
    const float* ob1    = (const float*)d_in[9];
    const float* ow2    = (const float*)d_in[10];
    const float* ob2    = (const float*)d_in[11];
    const float* ow3    = (const float*)d_in[12];
    const float* ob3    = (const float*)d_in[13];
    float* out = (float*)d_out;

    void *pahi, *palo, *pbhi, *pblo, *poff, *pmask, *pxt, *pwd;
    void *pw1h, *pw1l, *pw2h, *pw2l, *pw3h, *pw3l;
    cudaGetSymbolAddress(&pahi, g_ha_hi);  cudaGetSymbolAddress(&palo, g_ha_lo);
    cudaGetSymbolAddress(&pbhi, g_hb_hi);  cudaGetSymbolAddress(&pblo, g_hb_lo);
    cudaGetSymbolAddress(&poff, g_off);    cudaGetSymbolAddress(&pmask, g_mask);
    cudaGetSymbolAddress(&pxt, g_xt);      cudaGetSymbolAddress(&pwd, g_wd);
    cudaGetSymbolAddress(&pw1h, g_w1hi);   cudaGetSymbolAddress(&pw1l, g_w1lo);
    cudaGetSymbolAddress(&pw2h, g_w2hi);   cudaGetSymbolAddress(&pw2l, g_w2lo);
    cudaGetSymbolAddress(&pw3h, g_w3hi);   cudaGetSymbolAddress(&pw3l, g_w3lo);

    float *ahi = (float*)pahi, *alo = (float*)palo;
    float *bhi = (float*)pbhi, *blo = (float*)pblo;
    float *offb = (float*)poff, *maskb = (float*)pmask;
    float *xtb = (float*)pxt, *wdb = (float*)pwd;

    transpose_x_kernel<<<dim3(12, 96, BATCH), dim3(32, 8)>>>(x, xtb);
    prep_wd_kernel<<<288, 256>>>(weight, wdb);
    prep_wsplit_kernel<<<(9 * 64 * 64 + 255) / 256, 256>>>(ow1, (float*)pw1h, (float*)pw1l, 64, 64);
    prep_wsplit_kernel<<<(9 * 64 * 64 + 255) / 256, 256>>>(ow2, (float*)pw2h, (float*)pw2l, 64, 64);
    prep_wsplit_kernel<<<(9 * 448 * 64 + 255) / 256, 256>>>(ow3, (float*)pw3h, (float*)pw3l, 432, 448);

    conv0_kernel<<<dim3(12, 16, BATCH), 96>>>(extra, flow1, flow2, ow0, ob0, ahi, alo);

    cudaFuncSetAttribute(tconv_kernel<0, 64>, cudaFuncAttributeMaxDynamicSharedMemorySize, TCM_SMEM);
    cudaFuncSetAttribute(tconv_kernel<1, 448>, cudaFuncAttributeMaxDynamicSharedMemorySize, TCM_SMEM);

    // conv1: ha -> hb
    tconv_kernel<0, 64><<<dim3(NTILE, 1, BATCH), 128, TCM_SMEM>>>(
        ahi, alo, (float*)pw1h, (float*)pw1l, ob1, bhi, blo,
        nullptr, nullptr, nullptr, nullptr);
    // conv2: hb -> ha
    tconv_kernel<0, 64><<<dim3(NTILE, 1, BATCH), 128, TCM_SMEM>>>(
        bhi, blo, (float*)pw2h, (float*)pw2l, ob2, ahi, alo,
        nullptr, nullptr, nullptr, nullptr);
    // conv3: ha -> offset/mask
    tconv_kernel<1, 448><<<dim3(NTILE, 7, BATCH), 128, TCM_SMEM>>>(
        ahi, alo, (float*)pw3h, (float*)pw3l, ob3, nullptr, nullptr,
        offb, maskb, flow1, flow2);

    int smem = 16 * SSTRIDE * (int)sizeof(float);
    cudaFuncSetAttribute(deform_kernel, cudaFuncAttributeMaxDynamicSharedMemorySize, smem);
    deform_kernel<<<dim3(6, 96, BATCH), 256, smem>>>(xtb, offb, maskb, wdb, bias, out);
}

// round 13
// speedup vs baseline: 1.0915x; 1.0915x over previous
#include <cuda_runtime.h>
#include <cuda_pipeline.h>
#include <math.h>
#include <stdint.h>

#define HH 96
#define WW 96
#define HW 9216
#define BATCH 4
#define PSTRIDE 9984      // padded-NHWC pixels per batch image
#define PBASE 128         // front guard (>= 99)
#define NTILE 76          // 76 tiles of 128 padded pixels cover 98*98=9604

typedef unsigned long long ull;

// ---------------- scratch (static device globals; zero-initialized) ----------------
__device__ float g_ha_hi[BATCH * PSTRIDE * 64];
__device__ float g_ha_lo[BATCH * PSTRIDE * 64];
__device__ float g_hb_hi[BATCH * PSTRIDE * 64];
__device__ float g_hb_lo[BATCH * PSTRIDE * 64];
__device__ float g_off[BATCH * 288 * HW];
__device__ float g_mask[BATCH * 144 * HW];
__device__ float g_xt[BATCH * HW * 128];
__device__ float g_wd[1152 * 64];
__device__ float g_w1hi[9 * 64 * 64],  g_w1lo[9 * 64 * 64];
__device__ float g_w2hi[9 * 64 * 64],  g_w2lo[9 * 64 * 64];
__device__ float g_w3hi[9 * 448 * 64], g_w3lo[9 * 448 * 64];   // rows 432..447 stay zero

// ---------------- packed f32x2 helpers ----------------
__device__ __forceinline__ void fma2(ull& d, ull a, ull b) {
    asm("fma.rn.f32x2 %0, %1, %2, %0;" : "+l"(d) : "l"(a), "l"(b));
}
__device__ __forceinline__ ull pack2(float lo, float hi) {
    ull r; asm("mov.b64 %0, {%1, %2};" : "=l"(r) : "f"(lo), "f"(hi)); return r;
}
__device__ __forceinline__ void unpack2(ull p, float& lo, float& hi) {
    asm("mov.b64 {%0, %1}, %2;" : "=f"(lo), "=f"(hi) : "l"(p));
}
__device__ __forceinline__ ull midpair(ull a, ull b) { return (a >> 32) | (b << 32); }

// ---------------- tf32 split ----------------
__device__ __forceinline__ void tsplit(float v, float& h, float& l) {
    uint32_t hb; asm("cvt.rna.tf32.f32 %0, %1;" : "=r"(hb) : "f"(v));
    h = __uint_as_float(hb);
    float r = v - h;
    uint32_t lb; asm("cvt.rna.tf32.f32 %0, %1;" : "=r"(lb) : "f"(r));
    l = __uint_as_float(lb);
}

// ---------------- warp mma m16n8k8 tf32 ----------------
__device__ __forceinline__ void mma8(float* c, const uint32_t* a, const uint32_t* b) {
    asm volatile(
        "mma.sync.aligned.m16n8k8.row.col.f32.tf32.tf32.f32 "
        "{%0,%1,%2,%3}, {%4,%5,%6,%7}, {%8,%9}, {%0,%1,%2,%3};"
        : "+f"(c[0]), "+f"(c[1]), "+f"(c[2]), "+f"(c[3])
        : "r"(a[0]), "r"(a[1]), "r"(a[2]), "r"(a[3]), "r"(b[0]), "r"(b[1]));
}

// ---------------- transpose x: NCHW -> N(HW)C ----------------
__global__ void transpose_x_kernel(const float* __restrict__ x, float* __restrict__ xt) {
    __shared__ float t[32][33];
    int b = blockIdx.z, y = blockIdx.y;
    int c0 = (blockIdx.x & 3) * 32;
    int w0 = (blockIdx.x >> 2) * 32;
    int tx = threadIdx.x, ty = threadIdx.y;
#pragma unroll
    for (int j = 0; j < 4; j++) {
        int c = c0 + ty + j * 8;
        t[ty + j * 8][tx] = x[((b * 128 + c) * HH + y) * WW + w0 + tx];
    }
    __syncthreads();
#pragma unroll
    for (int j = 0; j < 4; j++) {
        int w = w0 + ty + j * 8;
        xt[((size_t)b * HW + (size_t)y * WW + w) * 128 + c0 + tx] = t[tx][ty + j * 8];
    }
}

// ---------------- deform-weight transpose ----------------
__global__ void prep_wd_kernel(const float* __restrict__ wgt, float* __restrict__ wd) {
    int i = blockIdx.x * 256 + threadIdx.x;
    int kk = i >> 6, o = i & 63;
    int g = kk / 72, r = kk - g * 72;
    int k = r >> 3, c = r & 7;
    wd[i] = wgt[(o * 128 + g * 8 + c) * 9 + k];
}

// ---------------- conv weight hi/lo split -> [tap][oc(OCP)][64ch] ----------------
__global__ void prep_wsplit_kernel(const float* __restrict__ src, float* __restrict__ hi,
                                   float* __restrict__ lo, int OC, int OCP) {
    int i = blockIdx.x * 256 + threadIdx.x;
    int n = 9 * OCP * 64;
    if (i >= n) return;
    int c = i & 63;
    int rest = i >> 6;
    int oc = rest % OCP;
    int tap = rest / OCP;
    if (oc >= OC) return;
    float w = src[((oc * 64 + c) * 3 + tap / 3) * 3 + (tap % 3)];
    float h, l;
    tsplit(w, h, l);
    hi[i] = h;
    lo[i] = l;
}

// ---------------- conv0: scalar f32x2 (CIN=196 concat) -> padded NHWC hi/lo ----------------
#define SROW 104
__global__ __launch_bounds__(96) void conv0_kernel(
    const float* __restrict__ extra,
    const float* __restrict__ flow1,
    const float* __restrict__ flow2,
    const float* __restrict__ wgt,
    const float* __restrict__ bias,
    float* __restrict__ outhi,
    float* __restrict__ outlo)
{
    const int CIN = 196;
    __shared__ float s_in[3][4][10][SROW];
    __shared__ float2 s_w2[3][144];

    const int b = blockIdx.z;
    const int oc0 = blockIdx.y * 4;
    const int gy0 = blockIdx.x * 8;
    const int tid = threadIdx.x;
    const int tx = tid % 48;
    const int ty = tid / 48;
    const int nsteps = CIN / 4;

    const float4 z4 = make_float4(0.f, 0.f, 0.f, 0.f);
    for (int i = tid; i < 240; i += 96) {
        int bi = i / 80, rem = i % 80;
        int ck = rem / 20, rem2 = rem % 20;
        int r = rem2 >> 1, side = rem2 & 1;
        *(float4*)&s_in[bi][ck][r][side ? 100 : 0] = z4;
    }
    if (gy0 == 0 || gy0 == 88) {
        int rr = (gy0 == 0) ? 0 : 9;
        for (int i = tid; i < 312; i += 96) {
            int bi = i / 104, rem = i % 104;
            int ck = rem / 26, q = rem % 26;
            ((float4*)&s_in[bi][ck][rr][0])[q] = z4;
        }
    }

    int soff[10], doff[10];
    unsigned vmask = 0;
#pragma unroll
    for (int i = 0; i < 10; i++) {
        int t = tid + 96 * i;
        int q = t % 24, rc = t / 24;
        int ck = rc / 10, rr = rc - ck * 10;
        int gy = gy0 + rr - 1;
        soff[i] = ck * HW + gy * WW + 4 * q;
        doff[i] = rc * SROW + 4 + 4 * q;
        if ((unsigned)gy < (unsigned)HH) vmask |= 1u << i;
    }

    const int t0 = tid, t1 = tid + 96;
    const int o_0 = t0 / 36, ck_0 = (t0 % 36) / 9, k_0 = t0 % 9;
    const int o_1 = t1 / 36, ck_1 = (t1 % 36) / 9, k_1 = t1 % 9;
    const int wi0 = ((oc0 + o_0) * CIN + ck_0) * 9 + k_0;
    const int wi1 = ((oc0 + o_1) * CIN + ck_1) * 9 + k_1;

#define C0_STAGE(BI, C0)                                                                 \
    do {                                                                                 \
        float* db = &s_in[BI][0][0][0];                                                  \
        if ((C0) < 192) {                                                                \
            const float* base = extra + (size_t)(b * 192 + (C0)) * HW;                   \
            _Pragma("unroll")                                                            \
            for (int i = 0; i < 10; i++)                                                 \
                if ((vmask >> i) & 1)                                                    \
                    __pipeline_memcpy_async(db + doff[i], base + soff[i], 16);           \
        } else {                                                                         \
            _Pragma("unroll")                                                            \
            for (int i = 0; i < 10; i++) {                                               \
                if ((vmask >> i) & 1) {                                                  \
                    int t = tid + 96 * i;                                                \
                    int q = t % 24, rc = t / 24;                                         \
                    int ck = rc / 10, rr = rc - ck * 10;                                 \
                    int gy = gy0 + rr - 1;                                               \
                    const float* src = ((ck < 2) ? flow1 : flow2)                        \
                                       + (size_t)(b * 2 + (ck & 1)) * HW;                \
                    __pipeline_memcpy_async(db + doff[i], src + gy * WW + 4 * q, 16);    \
                }                                                                        \
            }                                                                            \
        }                                                                                \
    } while (0)

#define C0_STAGE_W(BI, C0)                                                               \
    do {                                                                                 \
        float w = wgt[wi0 + (C0) * 9];                                                   \
        s_w2[BI][t0] = make_float2(w, w);                                                \
        if (t1 < 144) {                                                                  \
            float w2v = wgt[wi1 + (C0) * 9];                                             \
            s_w2[BI][t1] = make_float2(w2v, w2v);                                        \
        }                                                                                \
    } while (0)

    C0_STAGE(0, 0);
    __pipeline_commit();
    C0_STAGE_W(0, 0);

    ull acc[4][4];
#pragma unroll
    for (int o = 0; o < 4; o++)
#pragma unroll
        for (int r = 0; r < 4; r++) acc[o][r] = 0ULL;

    int cur = 0;
    for (int s = 0; s < nsteps; s++) {
        int nxt = (cur == 2) ? 0 : cur + 1;
        if (s + 1 < nsteps) {
            const int c0n = (s + 1) * 4;
            C0_STAGE(nxt, c0n);
            __pipeline_commit();
            C0_STAGE_W(nxt, c0n);
            __pipeline_wait_prior(1);
        } else {
            __pipeline_wait_prior(0);
        }
        __syncthreads();

#pragma unroll
        for (int ck = 0; ck < 4; ck++) {
            ull P[6][3];
#pragma unroll
            for (int iy = 0; iy < 6; iy++) {
                const float* rp = &s_in[cur][ck][ty * 4 + iy][2 + 2 * tx];
                ull a = *(const ull*)rp;
                ull bb = *(const ull*)(rp + 2);
                ull c = *(const ull*)(rp + 4);
                P[iy][0] = midpair(a, bb);
                P[iy][1] = bb;
                P[iy][2] = midpair(bb, c);
            }
#pragma unroll
            for (int o = 0; o < 4; o++) {
                const float2* wrow = &s_w2[cur][o * 36 + ck * 9];
#pragma unroll
                for (int ky = 0; ky < 3; ky++)
#pragma unroll
                    for (int kx = 0; kx < 3; kx++) {
                        ull w2 = *(const ull*)&wrow[ky * 3 + kx];
#pragma unroll
                        for (int r = 0; r < 4; r++)
                            fma2(acc[o][r], P[r + ky][kx], w2);
                    }
            }
        }
        cur = nxt;
    }

#pragma unroll
    for (int o = 0; o < 4; o++) {
        int oc = oc0 + o;
        float bv = bias[oc];
#pragma unroll
        for (int rr = 0; rr < 4; rr++) {
            int gy = gy0 + ty * 4 + rr;
            int gx = 2 * tx;
            float v0, v1;
            unpack2(acc[o][rr], v0, v1);
            v0 += bv; v1 += bv;
            v0 = (v0 >= 0.f) ? v0 : 0.1f * v0;
            v1 = (v1 >= 0.f) ? v1 : 0.1f * v1;
            float h0, l0, h1, l1;
            tsplit(v0, h0, l0);
            tsplit(v1, h1, l1);
            size_t pb = ((size_t)b * PSTRIDE + PBASE + (gy + 1) * 98 + (gx + 1)) * 64 + oc;
            outhi[pb] = h0;      outlo[pb] = l0;
            outhi[pb + 64] = h1; outlo[pb + 64] = l1;
        }
    }
#undef C0_STAGE
#undef C0_STAGE_W
}

// ---------------- tensor conv via warp mma: 9-tap split-TF32 GEMM ----------------
// block 256 (8 warps, 2/SMSP); tile 128 px x 64 oc; warp = 32 px x 32 oc.
// smem: A window 326 rows x 68 floats (hi+lo) resident; B 64x68 (hi+lo) per tap.
// B for next tap prefetched through registers during MMA.
#define APAD 68
#define ABYTES (326 * APAD * 4)
#define OFF_AL ABYTES
#define OFF_BH (2 * ABYTES)
#define OFF_BL (2 * ABYTES + 64 * APAD * 4)
#define TCM_SMEM (OFF_BL + 64 * APAD * 4)

template <int EPI, int OCP>
__global__ __launch_bounds__(256) void tconv_kernel(
    const float* __restrict__ inhi, const float* __restrict__ inlo,
    const float* __restrict__ wbhi, const float* __restrict__ wblo,
    const float* __restrict__ bias,
    float* __restrict__ outhi, float* __restrict__ outlo,
    float* __restrict__ offb, float* __restrict__ maskb,
    const float* __restrict__ flow1, const float* __restrict__ flow2)
{
    extern __shared__ __align__(16) char smem[];
    float* Ah = (float*)smem;
    float* Al = (float*)(smem + OFF_AL);
    float* Bh = (float*)(smem + OFF_BH);
    float* Bl = (float*)(smem + OFF_BL);

    const int tid = threadIdx.x;
    const int wid = tid >> 5, lane = tid & 31;
    const int gid = lane >> 2, tig = lane & 3;
    const int pxb = (wid & 3) * 32;       // warp pixel base within tile
    const int ocb = (wid >> 2) * 32;      // warp oc base within 64-oc slice
    const int b = blockIdx.z, occ = blockIdx.y;
    const int p0 = blockIdx.x * 128;
    const size_t bb = (size_t)b * PSTRIDE + PBASE;

    // ---- stage A window rows [p0-99, p0+227): 326 rows x 16 chunks x {hi,lo} ----
    {
        const size_t rowbase = bb + p0 - 99;
#pragma unroll 1
        for (int i = 0; i < 41; i++) {
            int cc = tid + 256 * i;
            if (cc >= 10432) break;
            int h = cc / 5216, rem = cc - h * 5216;
            int r = rem >> 4, q = rem & 15;
            float* dst = (h ? Al : Ah) + r * APAD + q * 4;
            const float* src = (h ? inlo : inhi) + (rowbase + r) * 64 + q * 4;
            __pipeline_memcpy_async(dst, src, 16);
        }
    }
    // ---- stage B tap 0 ----
    {
        const size_t brow = (size_t)occ * 64;
#pragma unroll
        for (int i = 0; i < 8; i++) {
            int cc = tid + 256 * i;
            int h = cc >> 10, rem = cc & 1023;
            int r = rem >> 4, q = rem & 15;
            float* dst = (h ? Bl : Bh) + r * APAD + q * 4;
            const float* src = (h ? wblo : wbhi) + (brow + r) * 64 + q * 4;
            __pipeline_memcpy_async(dst, src, 16);
        }
    }
    __pipeline_commit();
    __pipeline_wait_prior(0);
    __syncthreads();

    float acc[2][4][4];
#pragma unroll
    for (int mt = 0; mt < 2; mt++)
#pragma unroll
        for (int nt = 0; nt < 4; nt++)
#pragma unroll
            for (int e = 0; e < 4; e++) acc[mt][nt][e] = 0.f;

    // B prefetch decomposition (constant per thread)
    int pfh[8], pfr[8], pfq[8];
#pragma unroll
    for (int i = 0; i < 8; i++) {
        int cc = tid + 256 * i;
        pfh[i] = cc >> 10;
        pfr[i] = (cc & 1023) >> 4;
        pfq[i] = cc & 15;
    }

    for (int tap = 0; tap < 9; tap++) {
        // prefetch next tap's B into registers (latency hidden by MMA below)
        float4 pre[8];
        if (tap < 8) {
            const size_t brow = (size_t)(tap + 1) * OCP + occ * 64;
#pragma unroll
            for (int i = 0; i < 8; i++) {
                const float* src = (pfh[i] ? wblo : wbhi) + (brow + pfr[i]) * 64 + pfq[i] * 4;
                pre[i] = *(const float4*)src;
            }
        }

        const int shift = (tap / 3 - 1) * 98 + (tap % 3) - 1;
        const int abase0 = (pxb + gid + 99 + shift) * APAD + tig;

#pragma unroll
        for (int ks = 0; ks < 8; ks++) {
            const int k = ks * 8;
            uint32_t ahf[2][4], alf[2][4], bhf[4][2], blf[4][2];
#pragma unroll
            for (int mt = 0; mt < 2; mt++) {
                int base = abase0 + mt * 16 * APAD + k;
                ahf[mt][0] = __float_as_uint(Ah[base]);
                ahf[mt][1] = __float_as_uint(Ah[base + 8 * APAD]);
                ahf[mt][2] = __float_as_uint(Ah[base + 4]);
                ahf[mt][3] = __float_as_uint(Ah[base + 8 * APAD + 4]);
                alf[mt][0] = __float_as_uint(Al[base]);
                alf[mt][1] = __float_as_uint(Al[base + 8 * APAD]);
                alf[mt][2] = __float_as_uint(Al[base + 4]);
                alf[mt][3] = __float_as_uint(Al[base + 8 * APAD + 4]);
            }
#pragma unroll
            for (int nt = 0; nt < 4; nt++) {
                int bbase = (ocb + nt * 8 + gid) * APAD + k + tig;
                bhf[nt][0] = __float_as_uint(Bh[bbase]);
                bhf[nt][1] = __float_as_uint(Bh[bbase + 4]);
                blf[nt][0] = __float_as_uint(Bl[bbase]);
                blf[nt][1] = __float_as_uint(Bl[bbase + 4]);
            }
#pragma unroll
            for (int mt = 0; mt < 2; mt++)
#pragma unroll
                for (int nt = 0; nt < 4; nt++) {
                    mma8(acc[mt][nt], ahf[mt], bhf[nt]);
                    mma8(acc[mt][nt], ahf[mt], blf[nt]);
                    mma8(acc[mt][nt], alf[mt], bhf[nt]);
                }
        }

        if (tap < 8) {
            __syncthreads();   // all warps done reading B(tap)
#pragma unroll
            for (int i = 0; i < 8; i++) {
                float* dst = (pfh[i] ? Bl : Bh) + pfr[i] * APAD + pfq[i] * 4;
                *(float4*)dst = pre[i];
            }
            __syncthreads();   // B(tap+1) visible
        }
    }

    // ---- epilogue ----
#pragma unroll
    for (int mt = 0; mt < 2; mt++) {
#pragma unroll
        for (int half = 0; half < 2; half++) {
            int pp = p0 + pxb + mt * 16 + gid + half * 8;
            int r98 = pp / 98, c98 = pp - r98 * 98;
            bool valid = (r98 >= 1) && (r98 <= 96) && (c98 >= 1) && (c98 <= 96);
            if (!valid) continue;
            if (EPI == 0) {
                size_t ob = (bb + pp) * 64;
#pragma unroll
                for (int nt = 0; nt < 4; nt++) {
                    int oc = ocb + nt * 8 + tig * 2;
                    float v0 = acc[mt][nt][half * 2 + 0] + __ldg(&bias[oc]);
                    float v1 = acc[mt][nt][half * 2 + 1] + __ldg(&bias[oc + 1]);
                    v0 = (v0 >= 0.f) ? v0 : 0.1f * v0;
                    v1 = (v1 >= 0.f) ? v1 : 0.1f * v1;
                    float h0, l0, h1, l1;
                    tsplit(v0, h0, l0);
                    tsplit(v1, h1, l1);
                    *(float2*)&outhi[ob + oc] = make_float2(h0, h1);
                    *(float2*)&outlo[ob + oc] = make_float2(l0, l1);
                }
            } else {
                int y = r98 - 1, x = c98 - 1;
                int pix = y * WW + x;
                float f1a = __ldg(&flow1[(size_t)(b * 2 + 0) * HW + pix]);
                float f1b = __ldg(&flow1[(size_t)(b * 2 + 1) * HW + pix]);
                float f2a = __ldg(&flow2[(size_t)(b * 2 + 0) * HW + pix]);
                float f2b = __ldg(&flow2[(size_t)(b * 2 + 1) * HW + pix]);
#pragma unroll
                for (int nt = 0; nt < 4; nt++) {
#pragma unroll
                    for (int e = 0; e < 2; e++) {
                        int oc = occ * 64 + ocb + nt * 8 + tig * 2 + e;
                        if (oc >= 432) continue;
                        float v = acc[mt][nt][half * 2 + e] + __ldg(&bias[oc]);
                        if (oc < 288) {
                            int par = 1 - (oc & 1);
                            float f = (oc < 144) ? (par ? f1b : f1a) : (par ? f2b : f2a);
                            offb[((size_t)b * 288 + oc) * HW + pix] = 10.f * tanhf(v) + f;
                        } else {
                            maskb[((size_t)b * 144 + (oc - 288)) * HW + pix] =
                                1.f / (1.f + expf(-v));
                        }
                    }
                }
            }
        }
    }
}

// ---------------- deformable conv (unchanged) ----------------
#define SSTRIDE 1156

__global__ void deform_kernel(
    const float* __restrict__ xt,
    const float* __restrict__ off,
    const float* __restrict__ msk,
    const float* __restrict__ wd,
    const float* __restrict__ bias,
    float* __restrict__ out)
{
    extern __shared__ float s_sm[];
    int b = blockIdx.z;
    int h = blockIdx.y;
    int w0 = blockIdx.x * 16;
    int tid = threadIdx.x;
    {
        int px = tid & 15;
        int ww = w0 + px;
        int pospix = h * WW + ww;
        const float* offb = off + (size_t)b * 288 * HW + pospix;
        const float* mskb = msk + (size_t)b * 144 * HW + pospix;
        const float* xb = xt + (size_t)b * HW * 128;
#pragma unroll 1
        for (int it = 0; it < 9; it++) {
            int gk = (tid >> 4) + it * 16;
            int g = gk / 9, k = gk - g * 9;
            int ky = k / 3, kx = k - ky * 3;
            int oc = g * 18 + k * 2;
            float dy = offb[(size_t)oc * HW];
            float dx = offb[(size_t)(oc + 1) * HW];
            float m = mskb[(size_t)gk * HW];
            float py = dy + (float)(ky + h - 1);
            float pxx = dx + (float)(kx + ww - 1);
            float fy0 = floorf(py), fx0 = floorf(pxx);
            float wy1 = py - fy0, wx1 = pxx - fx0;
            int iy0 = (int)fy0, ix0 = (int)fx0;
            float a[8];
#pragma unroll
            for (int i = 0; i < 8; i++) a[i] = 0.f;
#pragma unroll
            for (int dyc = 0; dyc < 2; dyc++) {
#pragma unroll
                for (int dxc = 0; dxc < 2; dxc++) {
                    int yy = iy0 + dyc, xx = ix0 + dxc;
                    if ((unsigned)yy < HH && (unsigned)xx < WW) {
                        float wc = (dyc ? wy1 : 1.f - wy1) * (dxc ? wx1 : 1.f - wx1);
                        const float4* p = (const float4*)(xb + ((size_t)yy * WW + xx) * 128 + g * 8);
                        float4 v0 = p[0], v1 = p[1];
                        a[0] += wc * v0.x; a[1] += wc * v0.y; a[2] += wc * v0.z; a[3] += wc * v0.w;
                        a[4] += wc * v1.x; a[5] += wc * v1.y; a[6] += wc * v1.z; a[7] += wc * v1.w;
                    }
                }
            }
            float* sp = s_sm + px * SSTRIDE + g * 72 + k * 8;
            ((float4*)sp)[0] = make_float4(a[0] * m, a[1] * m, a[2] * m, a[3] * m);
            ((float4*)sp)[1] = make_float4(a[4] * m, a[5] * m, a[6] * m, a[7] * m);
        }
    }
    __syncthreads();
    {
        int og = tid & 15;
        int p2 = tid >> 4;
        const ulonglong2* wdv = (const ulonglong2*)wd;
        const float4* sr4 = (const float4*)(s_sm + p2 * SSTRIDE);
        float4 bbv = ((const float4*)bias)[og];
        ull a01 = pack2(bbv.x, bbv.y);
        ull a23 = pack2(bbv.z, bbv.w);
#pragma unroll 2
        for (int kk4 = 0; kk4 < 288; kk4++) {
            float4 sv = sr4[kk4];
            { ull ss = pack2(sv.x, sv.x); ulonglong2 wv = wdv[(kk4 * 4 + 0) * 16 + og];
              fma2(a01, wv.x, ss); fma2(a23, wv.y, ss); }
            { ull ss = pack2(sv.y, sv.y); ulonglong2 wv = wdv[(kk4 * 4 + 1) * 16 + og];
              fma2(a01, wv.x, ss); fma2(a23, wv.y, ss); }
            { ull ss = pack2(sv.z, sv.z); ulonglong2 wv = wdv[(kk4 * 4 + 2) * 16 + og];
              fma2(a01, wv.x, ss); fma2(a23, wv.y, ss); }
            { ull ss = pack2(sv.w, sv.w); ulonglong2 wv = wdv[(kk4 * 4 + 3) * 16 + og];
              fma2(a01, wv.x, ss); fma2(a23, wv.y, ss); }
        }
        float r0, r1, r2, r3;
        unpack2(a01, r0, r1);
        unpack2(a23, r2, r3);
        int oc = og * 4;
        size_t ob = (size_t)b * 64 * HW + (size_t)h * WW + w0 + p2;
        out[ob + (size_t)(oc + 0) * HW] = r0;
        out[ob + (size_t)(oc + 1) * HW] = r1;
        out[ob + (size_t)(oc + 2) * HW] = r2;
        out[ob + (size_t)(oc + 3) * HW] = r3;
    }
}

// ---------------- launch ----------------
extern "C" void kernel_launch(void* const* d_in, const int* in_sizes, int n_in,
                              void* d_out, int out_size)
{
    const float* x      = (const float*)d_in[0];
    const float* extra  = (const float*)d_in[1];
    const float* flow1  = (const float*)d_in[2];
    const float* flow2  = (const float*)d_in[3];
    const float* weight = (const float*)d_in[4];
    const float* bias   = (const float*)d_in[5];
    const float* ow0    = (const float*)d_in[6];
    const float* ob0    = (const float*)d_in[7];
    const float* ow1    = (const float*)d_in[8];
    const float* ob1    = (const float*)d_in[9];
    const float* ow2    = (const float*)d_in[10];
    const float* ob2    = (const float*)d_in[11];
    const float* ow3    = (const float*)d_in[12];
    const float* ob3    = (const float*)d_in[13];
    float* out = (float*)d_out;

    void *pahi, *palo, *pbhi, *pblo, *poff, *pmask, *pxt, *pwd;
    void *pw1h, *pw1l, *pw2h, *pw2l, *pw3h, *pw3l;
    cudaGetSymbolAddress(&pahi, g_ha_hi);  cudaGetSymbolAddress(&palo, g_ha_lo);
    cudaGetSymbolAddress(&pbhi, g_hb_hi);  cudaGetSymbolAddress(&pblo, g_hb_lo);
    cudaGetSymbolAddress(&poff, g_off);    cudaGetSymbolAddress(&pmask, g_mask);
    cudaGetSymbolAddress(&pxt, g_xt);      cudaGetSymbolAddress(&pwd, g_wd);
    cudaGetSymbolAddress(&pw1h, g_w1hi);   cudaGetSymbolAddress(&pw1l, g_w1lo);
    cudaGetSymbolAddress(&pw2h, g_w2hi);   cudaGetSymbolAddress(&pw2l, g_w2lo);
    cudaGetSymbolAddress(&pw3h, g_w3hi);   cudaGetSymbolAddress(&pw3l, g_w3lo);

    float *ahi = (float*)pahi, *alo = (float*)palo;
    float *bhi = (float*)pbhi, *blo = (float*)pblo;
    float *offb = (float*)poff, *maskb = (float*)pmask;
    float *xtb = (float*)pxt, *wdb = (float*)pwd;

    transpose_x_kernel<<<dim3(12, 96, BATCH), dim3(32, 8)>>>(x, xtb);
    prep_wd_kernel<<<288, 256>>>(weight, wdb);
    prep_wsplit_kernel<<<(9 * 64 * 64 + 255) / 256, 256>>>(ow1, (float*)pw1h, (float*)pw1l, 64, 64);
    prep_wsplit_kernel<<<(9 * 64 * 64 + 255) / 256, 256>>>(ow2, (float*)pw2h, (float*)pw2l, 64, 64);
    prep_wsplit_kernel<<<(9 * 448 * 64 + 255) / 256, 256>>>(ow3, (float*)pw3h, (float*)pw3l, 432, 448);

    conv0_kernel<<<dim3(12, 16, BATCH), 96>>>(extra, flow1, flow2, ow0, ob0, ahi, alo);

    cudaFuncSetAttribute(tconv_kernel<0, 64>, cudaFuncAttributeMaxDynamicSharedMemorySize, TCM_SMEM);
    cudaFuncSetAttribute(tconv_kernel<1, 448>, cudaFuncAttributeMaxDynamicSharedMemorySize, TCM_SMEM);

    // conv1: ha -> hb
    tconv_kernel<0, 64><<<dim3(NTILE, 1, BATCH), 256, TCM_SMEM>>>(
        ahi, alo, (float*)pw1h, (float*)pw1l, ob1, bhi, blo,
        nullptr, nullptr, nullptr, nullptr);
    // conv2: hb -> ha
    tconv_kernel<0, 64><<<dim3(NTILE, 1, BATCH), 256, TCM_SMEM>>>(
        bhi, blo, (float*)pw2h, (float*)pw2l, ob2, ahi, alo,
        nullptr, nullptr, nullptr, nullptr);
    // conv3: ha -> offset/mask
    tconv_kernel<1, 448><<<dim3(NTILE, 7, BATCH), 256, TCM_SMEM>>>(
        ahi, alo, (float*)pw3h, (float*)pw3l, ob3, nullptr, nullptr,
        offb, maskb, flow1, flow2);

    int smem = 16 * SSTRIDE * (int)sizeof(float);
    cudaFuncSetAttribute(deform_kernel, cudaFuncAttributeMaxDynamicSharedMemorySize, smem);
    deform_kernel<<<dim3(6, 96, BATCH), 256, smem>>>(xtb, offb, maskb, wdb, bias, out);
}

// round 14
// speedup vs baseline: 1.1932x; 1.0932x over previous
#include <cuda_runtime.h>
#include <cuda_pipeline.h>
#include <math.h>
#include <stdint.h>

#define HH 96
#define WW 96
#define HW 9216
#define BATCH 4
#define PSTRIDE 9984      // padded-NHWC pixels per batch image
#define PBASE 128         // front guard (>= 99)
#define NTILE 76          // 76 tiles of 128 padded pixels cover 98*98=9604

typedef unsigned long long ull;

// ---------------- scratch (static device globals; zero-initialized) ----------------
__device__ float g_ha_hi[BATCH * PSTRIDE * 64];
__device__ float g_ha_lo[BATCH * PSTRIDE * 64];
__device__ float g_hb_hi[BATCH * PSTRIDE * 64];
__device__ float g_hb_lo[BATCH * PSTRIDE * 64];
__device__ float g_ft_hi[4 * BATCH * PSTRIDE * 64];   // concat feat, chunk-major
__device__ float g_ft_lo[4 * BATCH * PSTRIDE * 64];
__device__ float g_off[BATCH * 288 * HW];
__device__ float g_mask[BATCH * 144 * HW];
__device__ float g_xt[BATCH * HW * 128];
__device__ float g_wd[1152 * 64];
__device__ float g_w0hi[4 * 9 * 64 * 64], g_w0lo[4 * 9 * 64 * 64];
__device__ float g_w1hi[9 * 64 * 64],  g_w1lo[9 * 64 * 64];
__device__ float g_w2hi[9 * 64 * 64],  g_w2lo[9 * 64 * 64];
__device__ float g_w3hi[9 * 448 * 64], g_w3lo[9 * 448 * 64];   // rows 432..447 stay zero

// ---------------- packed f32x2 helpers ----------------
__device__ __forceinline__ void fma2(ull& d, ull a, ull b) {
    asm("fma.rn.f32x2 %0, %1, %2, %0;" : "+l"(d) : "l"(a), "l"(b));
}
__device__ __forceinline__ ull pack2(float lo, float hi) {
    ull r; asm("mov.b64 %0, {%1, %2};" : "=l"(r) : "f"(lo), "f"(hi)); return r;
}
__device__ __forceinline__ void unpack2(ull p, float& lo, float& hi) {
    asm("mov.b64 {%0, %1}, %2;" : "=f"(lo), "=f"(hi) : "l"(p));
}

// ---------------- tf32 split ----------------
__device__ __forceinline__ void tsplit(float v, float& h, float& l) {
    uint32_t hb; asm("cvt.rna.tf32.f32 %0, %1;" : "=r"(hb) : "f"(v));
    h = __uint_as_float(hb);
    float r = v - h;
    uint32_t lb; asm("cvt.rna.tf32.f32 %0, %1;" : "=r"(lb) : "f"(r));
    l = __uint_as_float(lb);
}

// ---------------- warp mma m16n8k8 tf32 ----------------
__device__ __forceinline__ void mma8(float* c, const uint32_t* a, const uint32_t* b) {
    asm volatile(
        "mma.sync.aligned.m16n8k8.row.col.f32.tf32.tf32.f32 "
        "{%0,%1,%2,%3}, {%4,%5,%6,%7}, {%8,%9}, {%0,%1,%2,%3};"
        : "+f"(c[0]), "+f"(c[1]), "+f"(c[2]), "+f"(c[3])
        : "r"(a[0]), "r"(a[1]), "r"(a[2]), "r"(a[3]), "r"(b[0]), "r"(b[1]));
}

// ---------------- transpose x: NCHW -> N(HW)C ----------------
__global__ void transpose_x_kernel(const float* __restrict__ x, float* __restrict__ xt) {
    __shared__ float t[32][33];
    int b = blockIdx.z, y = blockIdx.y;
    int c0 = (blockIdx.x & 3) * 32;
    int w0 = (blockIdx.x >> 2) * 32;
    int tx = threadIdx.x, ty = threadIdx.y;
#pragma unroll
    for (int j = 0; j < 4; j++) {
        int c = c0 + ty + j * 8;
        t[ty + j * 8][tx] = x[((b * 128 + c) * HH + y) * WW + w0 + tx];
    }
    __syncthreads();
#pragma unroll
    for (int j = 0; j < 4; j++) {
        int w = w0 + ty + j * 8;
        xt[((size_t)b * HW + (size_t)y * WW + w) * 128 + c0 + tx] = t[tx][ty + j * 8];
    }
}

// ---------------- feat transform: concat(extra,flow1,flow2) -> padded NHWC hi/lo chunk-major ----------------
__global__ void prep_feat_kernel(
    const float* __restrict__ extra,
    const float* __restrict__ flow1,
    const float* __restrict__ flow2,
    float* __restrict__ fhi, float* __restrict__ flo)
{
    int b = blockIdx.z, y = blockIdx.y;
    int tx = threadIdx.x, ty = threadIdx.y;
    if (blockIdx.x < 18) {
        __shared__ float t[32][33];
        int wblk = blockIdx.x % 3, cg = blockIdx.x / 3;    // cg 0..5
        int w0 = wblk * 32;
#pragma unroll
        for (int j = 0; j < 4; j++) {
            int c = cg * 32 + ty + j * 8;
            t[ty + j * 8][tx] = extra[((size_t)(b * 192 + c)) * HW + y * WW + w0 + tx];
        }
        __syncthreads();
        int chunk = cg >> 1, coff = (cg & 1) * 32;
#pragma unroll
        for (int j = 0; j < 4; j++) {
            int w = w0 + ty + j * 8;
            int pixel = (y + 1) * 98 + (w + 1);
            float v = t[tx][ty + j * 8];
            float h, l;
            tsplit(v, h, l);
            size_t d = ((size_t)(chunk * BATCH + b) * PSTRIDE + PBASE + pixel) * 64 + coff + tx;
            fhi[d] = h;
            flo[d] = l;
        }
    } else {
        // flow channels -> chunk 3, coff 0..3
        int idx = ty * 32 + tx;
#pragma unroll
        for (int r = 0; r < 2; r++) {
            int ii = idx + 256 * r;
            if (ii < 384) {
                int w = ii % 96, cc = ii / 96;   // cc 0..3
                const float* src = (cc < 2 ? flow1 : flow2) + (size_t)(b * 2 + (cc & 1)) * HW;
                float v = src[y * WW + w];
                float h, l;
                tsplit(v, h, l);
                int pixel = (y + 1) * 98 + (w + 1);
                size_t d = ((size_t)(3 * BATCH + b) * PSTRIDE + PBASE + pixel) * 64 + cc;
                fhi[d] = h;
                flo[d] = l;
            }
        }
    }
}

// ---------------- deform-weight transpose ----------------
__global__ void prep_wd_kernel(const float* __restrict__ wgt, float* __restrict__ wd) {
    int i = blockIdx.x * 256 + threadIdx.x;
    int kk = i >> 6, o = i & 63;
    int g = kk / 72, r = kk - g * 72;
    int k = r >> 3, c = r & 7;
    wd[i] = wgt[(o * 128 + g * 8 + c) * 9 + k];
}

// ---------------- conv weight hi/lo split -> [tap][oc(OCP)][64ch] ----------------
__global__ void prep_wsplit_kernel(const float* __restrict__ src, float* __restrict__ hi,
                                   float* __restrict__ lo, int OC, int OCP) {
    int i = blockIdx.x * 256 + threadIdx.x;
    int n = 9 * OCP * 64;
    if (i >= n) return;
    int c = i & 63;
    int rest = i >> 6;
    int oc = rest % OCP;
    int tap = rest / OCP;
    if (oc >= OC) return;
    float w = src[((oc * 64 + c) * 3 + tap / 3) * 3 + (tap % 3)];
    float h, l;
    tsplit(w, h, l);
    hi[i] = h;
    lo[i] = l;
}

// ---------------- w0 split: ow0[oc][196][3][3] -> [chunk][tap][64oc][64ch] hi/lo ----------------
__global__ void prep_w0split_kernel(const float* __restrict__ src, float* __restrict__ hi,
                                    float* __restrict__ lo) {
    int i = blockIdx.x * 256 + threadIdx.x;
    if (i >= 4 * 9 * 64 * 64) return;
    int cc = i & 63;
    int rest = i >> 6;
    int oc = rest & 63;
    int rest2 = rest >> 6;
    int tap = rest2 % 9;
    int chunk = rest2 / 9;
    int c = chunk * 64 + cc;
    if (c >= 196) return;   // padded channels stay zero
    float w = src[((oc * 196 + c) * 3 + tap / 3) * 3 + (tap % 3)];
    float h, l;
    tsplit(w, h, l);
    hi[i] = h;
    lo[i] = l;
}

// ---------------- tensor conv via warp mma: 9-tap split-TF32 GEMM, NCHUNK k-chunks ----------------
// block 256 (8 warps, 2/SMSP); tile 128 px x 64 oc; warp = 32 px x 32 oc.
#define APAD 68
#define ABYTES (326 * APAD * 4)
#define OFF_AL ABYTES
#define OFF_BH (2 * ABYTES)
#define OFF_BL (2 * ABYTES + 64 * APAD * 4)
#define TCM_SMEM (OFF_BL + 64 * APAD * 4)

template <int EPI, int OCP, int NCHUNK, int KS_LAST>
__global__ __launch_bounds__(256) void tconv_kernel(
    const float* __restrict__ inhi, const float* __restrict__ inlo,
    const float* __restrict__ wbhi, const float* __restrict__ wblo,
    const float* __restrict__ bias,
    float* __restrict__ outhi, float* __restrict__ outlo,
    float* __restrict__ offb, float* __restrict__ maskb,
    const float* __restrict__ flow1, const float* __restrict__ flow2)
{
    extern __shared__ __align__(16) char smem[];
    float* Ah = (float*)smem;
    float* Al = (float*)(smem + OFF_AL);
    float* Bh = (float*)(smem + OFF_BH);
    float* Bl = (float*)(smem + OFF_BL);

    const int tid = threadIdx.x;
    const int wid = tid >> 5, lane = tid & 31;
    const int gid = lane >> 2, tig = lane & 3;
    const int pxb = (wid & 3) * 32;
    const int ocb = (wid >> 2) * 32;
    const int b = blockIdx.z, occ = blockIdx.y;
    const int p0 = blockIdx.x * 128;
    const size_t bb = (size_t)b * PSTRIDE + PBASE;
    const size_t ASTR = (size_t)BATCH * PSTRIDE * 64;   // chunk stride in A
    const int BSTR = 9 * OCP * 64;                      // chunk stride in B

    float acc[2][4][4];
#pragma unroll
    for (int mt = 0; mt < 2; mt++)
#pragma unroll
        for (int nt = 0; nt < 4; nt++)
#pragma unroll
            for (int e = 0; e < 4; e++) acc[mt][nt][e] = 0.f;

    // B prefetch decomposition (constant per thread)
    int pfh[8], pfr[8], pfq[8];
#pragma unroll
    for (int i = 0; i < 8; i++) {
        int cc = tid + 256 * i;
        pfh[i] = cc >> 10;
        pfr[i] = (cc & 1023) >> 4;
        pfq[i] = cc & 15;
    }

#pragma unroll 1
    for (int ch = 0; ch < NCHUNK; ch++) {
        if (ch) __syncthreads();   // all reads of previous chunk's A/B done

        const float* cAh = inhi + (size_t)ch * ASTR;
        const float* cAl = inlo + (size_t)ch * ASTR;
        const float* cBh = wbhi + (size_t)ch * BSTR;
        const float* cBl = wblo + (size_t)ch * BSTR;

        // ---- stage A window rows [p0-99, p0+227): 326 rows x 16 chunks x {hi,lo} ----
        {
            const size_t rowbase = bb + p0 - 99;
#pragma unroll 1
            for (int i = 0; i < 41; i++) {
                int cc = tid + 256 * i;
                if (cc >= 10432) break;
                int h = cc / 5216, rem = cc - h * 5216;
                int r = rem >> 4, q = rem & 15;
                float* dst = (h ? Al : Ah) + r * APAD + q * 4;
                const float* src = (h ? cAl : cAh) + (rowbase + r) * 64 + q * 4;
                __pipeline_memcpy_async(dst, src, 16);
            }
        }
        // ---- stage B tap 0 ----
        {
            const size_t brow = (size_t)occ * 64;
#pragma unroll
            for (int i = 0; i < 8; i++) {
                int cc = tid + 256 * i;
                int h = cc >> 10, rem = cc & 1023;
                int r = rem >> 4, q = rem & 15;
                float* dst = (h ? Bl : Bh) + r * APAD + q * 4;
                const float* src = (h ? cBl : cBh) + (brow + r) * 64 + q * 4;
                __pipeline_memcpy_async(dst, src, 16);
            }
        }
        __pipeline_commit();
        __pipeline_wait_prior(0);
        __syncthreads();

        const int KS = (ch == NCHUNK - 1) ? KS_LAST : 8;

#pragma unroll 1
        for (int tap = 0; tap < 9; tap++) {
            float4 pre[8];
            if (tap < 8) {
                const size_t brow = (size_t)(tap + 1) * OCP + occ * 64;
#pragma unroll
                for (int i = 0; i < 8; i++) {
                    const float* src = (pfh[i] ? cBl : cBh) + (brow + pfr[i]) * 64 + pfq[i] * 4;
                    pre[i] = *(const float4*)src;
                }
            }

            const int shift = (tap / 3 - 1) * 98 + (tap % 3) - 1;
            const int abase0 = (pxb + gid + 99 + shift) * APAD + tig;

#pragma unroll
            for (int ks = 0; ks < 8; ks++) {
                if (ks >= KS) break;
                const int k = ks * 8;
                uint32_t ahf[2][4], alf[2][4], bhf[4][2], blf[4][2];
#pragma unroll
                for (int mt = 0; mt < 2; mt++) {
                    int base = abase0 + mt * 16 * APAD + k;
                    ahf[mt][0] = __float_as_uint(Ah[base]);
                    ahf[mt][1] = __float_as_uint(Ah[base + 8 * APAD]);
                    ahf[mt][2] = __float_as_uint(Ah[base + 4]);
                    ahf[mt][3] = __float_as_uint(Ah[base + 8 * APAD + 4]);
                    alf[mt][0] = __float_as_uint(Al[base]);
                    alf[mt][1] = __float_as_uint(Al[base + 8 * APAD]);
                    alf[mt][2] = __float_as_uint(Al[base + 4]);
                    alf[mt][3] = __float_as_uint(Al[base + 8 * APAD + 4]);
                }
#pragma unroll
                for (int nt = 0; nt < 4; nt++) {
                    int bbase = (ocb + nt * 8 + gid) * APAD + k + tig;
                    bhf[nt][0] = __float_as_uint(Bh[bbase]);
                    bhf[nt][1] = __float_as_uint(Bh[bbase + 4]);
                    blf[nt][0] = __float_as_uint(Bl[bbase]);
                    blf[nt][1] = __float_as_uint(Bl[bbase + 4]);
                }
#pragma unroll
                for (int mt = 0; mt < 2; mt++)
#pragma unroll
                    for (int nt = 0; nt < 4; nt++) {
                        mma8(acc[mt][nt], ahf[mt], bhf[nt]);
                        mma8(acc[mt][nt], ahf[mt], blf[nt]);
                        mma8(acc[mt][nt], alf[mt], bhf[nt]);
                    }
            }

            if (tap < 8) {
                __syncthreads();
#pragma unroll
                for (int i = 0; i < 8; i++) {
                    float* dst = (pfh[i] ? Bl : Bh) + pfr[i] * APAD + pfq[i] * 4;
                    *(float4*)dst = pre[i];
                }
                __syncthreads();
            }
        }
    }

    // ---- epilogue ----
#pragma unroll
    for (int mt = 0; mt < 2; mt++) {
#pragma unroll
        for (int half = 0; half < 2; half++) {
            int pp = p0 + pxb + mt * 16 + gid + half * 8;
            int r98 = pp / 98, c98 = pp - r98 * 98;
            bool valid = (r98 >= 1) && (r98 <= 96) && (c98 >= 1) && (c98 <= 96);
            if (!valid) continue;
            if (EPI == 0) {
                size_t ob = (bb + pp) * 64;
#pragma unroll
                for (int nt = 0; nt < 4; nt++) {
                    int oc = ocb + nt * 8 + tig * 2;
                    float v0 = acc[mt][nt][half * 2 + 0] + __ldg(&bias[oc]);
                    float v1 = acc[mt][nt][half * 2 + 1] + __ldg(&bias[oc + 1]);
                    v0 = (v0 >= 0.f) ? v0 : 0.1f * v0;
                    v1 = (v1 >= 0.f) ? v1 : 0.1f * v1;
                    float h0, l0, h1, l1;
                    tsplit(v0, h0, l0);
                    tsplit(v1, h1, l1);
                    *(float2*)&outhi[ob + oc] = make_float2(h0, h1);
                    *(float2*)&outlo[ob + oc] = make_float2(l0, l1);
                }
            } else {
                int y = r98 - 1, x = c98 - 1;
                int pix = y * WW + x;
                float f1a = __ldg(&flow1[(size_t)(b * 2 + 0) * HW + pix]);
                float f1b = __ldg(&flow1[(size_t)(b * 2 + 1) * HW + pix]);
                float f2a = __ldg(&flow2[(size_t)(b * 2 + 0) * HW + pix]);
                float f2b = __ldg(&flow2[(size_t)(b * 2 + 1) * HW + pix]);
#pragma unroll
                for (int nt = 0; nt < 4; nt++) {
#pragma unroll
                    for (int e = 0; e < 2; e++) {
                        int oc = occ * 64 + ocb + nt * 8 + tig * 2 + e;
                        if (oc >= 432) continue;
                        float v = acc[mt][nt][half * 2 + e] + __ldg(&bias[oc]);
                        if (oc < 288) {
                            int par = 1 - (oc & 1);
                            float f = (oc < 144) ? (par ? f1b : f1a) : (par ? f2b : f2a);
                            offb[((size_t)b * 288 + oc) * HW + pix] = 10.f * tanhf(v) + f;
                        } else {
                            maskb[((size_t)b * 144 + (oc - 288)) * HW + pix] =
                                1.f / (1.f + expf(-v));
                        }
                    }
                }
            }
        }
    }
}

// ---------------- deformable conv (unchanged) ----------------
#define SSTRIDE 1156

__global__ void deform_kernel(
    const float* __restrict__ xt,
    const float* __restrict__ off,
    const float* __restrict__ msk,
    const float* __restrict__ wd,
    const float* __restrict__ bias,
    float* __restrict__ out)
{
    extern __shared__ float s_sm[];
    int b = blockIdx.z;
    int h = blockIdx.y;
    int w0 = blockIdx.x * 16;
    int tid = threadIdx.x;
    {
        int px = tid & 15;
        int ww = w0 + px;
        int pospix = h * WW + ww;
        const float* offb = off + (size_t)b * 288 * HW + pospix;
        const float* mskb = msk + (size_t)b * 144 * HW + pospix;
        const float* xb = xt + (size_t)b * HW * 128;
#pragma unroll 1
        for (int it = 0; it < 9; it++) {
            int gk = (tid >> 4) + it * 16;
            int g = gk / 9, k = gk - g * 9;
            int ky = k / 3, kx = k - ky * 3;
            int oc = g * 18 + k * 2;
            float dy = offb[(size_t)oc * HW];
            float dx = offb[(size_t)(oc + 1) * HW];
            float m = mskb[(size_t)gk * HW];
            float py = dy + (float)(ky + h - 1);
            float pxx = dx + (float)(kx + ww - 1);
            float fy0 = floorf(py), fx0 = floorf(pxx);
            float wy1 = py - fy0, wx1 = pxx - fx0;
            int iy0 = (int)fy0, ix0 = (int)fx0;
            float a[8];
#pragma unroll
            for (int i = 0; i < 8; i++) a[i] = 0.f;
#pragma unroll
            for (int dyc = 0; dyc < 2; dyc++) {
#pragma unroll
                for (int dxc = 0; dxc < 2; dxc++) {
                    int yy = iy0 + dyc, xx = ix0 + dxc;
                    if ((unsigned)yy < HH && (unsigned)xx < WW) {
                        float wc = (dyc ? wy1 : 1.f - wy1) * (dxc ? wx1 : 1.f - wx1);
                        const float4* p = (const float4*)(xb + ((size_t)yy * WW + xx) * 128 + g * 8);
                        float4 v0 = p[0], v1 = p[1];
                        a[0] += wc * v0.x; a[1] += wc * v0.y; a[2] += wc * v0.z; a[3] += wc * v0.w;
                        a[4] += wc * v1.x; a[5] += wc * v1.y; a[6] += wc * v1.z; a[7] += wc * v1.w;
                    }
                }
            }
            float* sp = s_sm + px * SSTRIDE + g * 72 + k * 8;
            ((float4*)sp)[0] = make_float4(a[0] * m, a[1] * m, a[2] * m, a[3] * m);
            ((float4*)sp)[1] = make_float4(a[4] * m, a[5] * m, a[6] * m, a[7] * m);
        }
    }
    __syncthreads();
    {
        int og = tid & 15;
        int p2 = tid >> 4;
        const ulonglong2* wdv = (const ulonglong2*)wd;
        const float4* sr4 = (const float4*)(s_sm + p2 * SSTRIDE);
        float4 bbv = ((const float4*)bias)[og];
        ull a01 = pack2(bbv.x, bbv.y);
        ull a23 = pack2(bbv.z, bbv.w);
#pragma unroll 2
        for (int kk4 = 0; kk4 < 288; kk4++) {
            float4 sv = sr4[kk4];
            { ull ss = pack2(sv.x, sv.x); ulonglong2 wv = wdv[(kk4 * 4 + 0) * 16 + og];
              fma2(a01, wv.x, ss); fma2(a23, wv.y, ss); }
            { ull ss = pack2(sv.y, sv.y); ulonglong2 wv = wdv[(kk4 * 4 + 1) * 16 + og];
              fma2(a01, wv.x, ss); fma2(a23, wv.y, ss); }
            { ull ss = pack2(sv.z, sv.z); ulonglong2 wv = wdv[(kk4 * 4 + 2) * 16 + og];
              fma2(a01, wv.x, ss); fma2(a23, wv.y, ss); }
            { ull ss = pack2(sv.w, sv.w); ulonglong2 wv = wdv[(kk4 * 4 + 3) * 16 + og];
              fma2(a01, wv.x, ss); fma2(a23, wv.y, ss); }
        }
        float r0, r1, r2, r3;
        unpack2(a01, r0, r1);
        unpack2(a23, r2, r3);
        int oc = og * 4;
        size_t ob = (size_t)b * 64 * HW + (size_t)h * WW + w0 + p2;
        out[ob + (size_t)(oc + 0) * HW] = r0;
        out[ob + (size_t)(oc + 1) * HW] = r1;
        out[ob + (size_t)(oc + 2) * HW] = r2;
        out[ob + (size_t)(oc + 3) * HW] = r3;
    }
}

// ---------------- launch ----------------
extern "C" void kernel_launch(void* const* d_in, const int* in_sizes, int n_in,
                              void* d_out, int out_size)
{
    const float* x      = (const float*)d_in[0];
    const float* extra  = (const float*)d_in[1];
    const float* flow1  = (const float*)d_in[2];
    const float* flow2  = (const float*)d_in[3];
    const float* weight = (const float*)d_in[4];
    const float* bias   = (const float*)d_in[5];
    const float* ow0    = (const float*)d_in[6];
    const float* ob0    = (const float*)d_in[7];
    const float* ow1    = (const float*)d_in[8];
    const float* ob1    = (const float*)d_in[9];
    const float* ow2    = (const float*)d_in[10];
    const float* ob2    = (const float*)d_in[11];
    const float* ow3    = (const float*)d_in[12];
    const float* ob3    = (const float*)d_in[13];
    float* out = (float*)d_out;

    void *pahi, *palo, *pbhi, *pblo, *pfhi, *pflo, *poff, *pmask, *pxt, *pwd;
    void *pw0h, *pw0l, *pw1h, *pw1l, *pw2h, *pw2l, *pw3h, *pw3l;
    cudaGetSymbolAddress(&pahi, g_ha_hi);  cudaGetSymbolAddress(&palo, g_ha_lo);
    cudaGetSymbolAddress(&pbhi, g_hb_hi);  cudaGetSymbolAddress(&pblo, g_hb_lo);
    cudaGetSymbolAddress(&pfhi, g_ft_hi);  cudaGetSymbolAddress(&pflo, g_ft_lo);
    cudaGetSymbolAddress(&poff, g_off);    cudaGetSymbolAddress(&pmask, g_mask);
    cudaGetSymbolAddress(&pxt, g_xt);      cudaGetSymbolAddress(&pwd, g_wd);
    cudaGetSymbolAddress(&pw0h, g_w0hi);   cudaGetSymbolAddress(&pw0l, g_w0lo);
    cudaGetSymbolAddress(&pw1h, g_w1hi);   cudaGetSymbolAddress(&pw1l, g_w1lo);
    cudaGetSymbolAddress(&pw2h, g_w2hi);   cudaGetSymbolAddress(&pw2l, g_w2lo);
    cudaGetSymbolAddress(&pw3h, g_w3hi);   cudaGetSymbolAddress(&pw3l, g_w3lo);

    float *ahi = (float*)pahi, *alo = (float*)palo;
    float *bhi = (float*)pbhi, *blo = (float*)pblo;
    float *fhi = (float*)pfhi, *flo = (float*)pflo;
    float *offb = (float*)poff, *maskb = (float*)pmask;
    float *xtb = (float*)pxt, *wdb = (float*)pwd;

    transpose_x_kernel<<<dim3(12, 96, BATCH), dim3(32, 8)>>>(x, xtb);
    prep_wd_kernel<<<288, 256>>>(weight, wdb);
    prep_w0split_kernel<<<(4 * 9 * 64 * 64 + 255) / 256, 256>>>(ow0, (float*)pw0h, (float*)pw0l);
    prep_wsplit_kernel<<<(9 * 64 * 64 + 255) / 256, 256>>>(ow1, (float*)pw1h, (float*)pw1l, 64, 64);
    prep_wsplit_kernel<<<(9 * 64 * 64 + 255) / 256, 256>>>(ow2, (float*)pw2h, (float*)pw2l, 64, 64);
    prep_wsplit_kernel<<<(9 * 448 * 64 + 255) / 256, 256>>>(ow3, (float*)pw3h, (float*)pw3l, 432, 448);
    prep_feat_kernel<<<dim3(19, 96, BATCH), dim3(32, 8)>>>(extra, flow1, flow2, fhi, flo);

    cudaFuncSetAttribute(tconv_kernel<0, 64, 4, 1>, cudaFuncAttributeMaxDynamicSharedMemorySize, TCM_SMEM);
    cudaFuncSetAttribute(tconv_kernel<0, 64, 1, 8>, cudaFuncAttributeMaxDynamicSharedMemorySize, TCM_SMEM);
    cudaFuncSetAttribute(tconv_kernel<1, 448, 1, 8>, cudaFuncAttributeMaxDynamicSharedMemorySize, TCM_SMEM);

    // conv0: feat -> ha   (4 K-chunks; last chunk 1 k-step)
    tconv_kernel<0, 64, 4, 1><<<dim3(NTILE, 1, BATCH), 256, TCM_SMEM>>>(
        fhi, flo, (float*)pw0h, (float*)pw0l, ob0, ahi, alo,
        nullptr, nullptr, nullptr, nullptr);
    // conv1: ha -> hb
    tconv_kernel<0, 64, 1, 8><<<dim3(NTILE, 1, BATCH), 256, TCM_SMEM>>>(
        ahi, alo, (float*)pw1h, (float*)pw1l, ob1, bhi, blo,
        nullptr, nullptr, nullptr, nullptr);
    // conv2: hb -> ha
    tconv_kernel<0, 64, 1, 8><<<dim3(NTILE, 1, BATCH), 256, TCM_SMEM>>>(
        bhi, blo, (float*)pw2h, (float*)pw2l, ob2, ahi, alo,
        nullptr, nullptr, nullptr, nullptr);
    // conv3: ha -> offset/mask
    tconv_kernel<1, 448, 1, 8><<<dim3(NTILE, 7, BATCH), 256, TCM_SMEM>>>(
        ahi, alo, (float*)pw3h, (float*)pw3l, ob3, nullptr, nullptr,
        offb, maskb, flow1, flow2);

    int smem = 16 * SSTRIDE * (int)sizeof(float);
    cudaFuncSetAttribute(deform_kernel, cudaFuncAttributeMaxDynamicSharedMemorySize, smem);
    deform_kernel<<<dim3(6, 96, BATCH), 256, smem>>>(xtb, offb, maskb, wdb, bias, out);
}

// round 15
// speedup vs baseline: 1.2151x; 1.0184x over previous
#include <cuda_runtime.h>
#include <cuda_pipeline.h>
#include <math.h>
#include <stdint.h>

#define HH 96
#define WW 96
#define HW 9216
#define BATCH 4
#define PSTRIDE 9984      // padded-NHWC pixels per batch image
#define PBASE 128         // front guard (>= 99)
#define NTILE 76          // 76 tiles of 128 padded pixels cover 98*98=9604

typedef unsigned long long ull;

// ---------------- scratch (static device globals; zero-initialized) ----------------
__device__ float g_ha_hi[BATCH * PSTRIDE * 64];
__device__ float g_ha_lo[BATCH * PSTRIDE * 64];
__device__ float g_hb_hi[BATCH * PSTRIDE * 64];
__device__ float g_hb_lo[BATCH * PSTRIDE * 64];
__device__ float g_ft_hi[4 * BATCH * PSTRIDE * 64];   // concat feat, chunk-major
__device__ float g_ft_lo[4 * BATCH * PSTRIDE * 64];
__device__ float g_off[BATCH * 288 * HW];
__device__ float g_mask[BATCH * 144 * HW];
__device__ float g_xt[BATCH * HW * 128];
__device__ float g_wd[1152 * 64];
__device__ float g_w0hi[4 * 9 * 64 * 64], g_w0lo[4 * 9 * 64 * 64];
__device__ float g_w1hi[9 * 64 * 64],  g_w1lo[9 * 64 * 64];
__device__ float g_w2hi[9 * 64 * 64],  g_w2lo[9 * 64 * 64];
__device__ float g_w3hi[9 * 448 * 64], g_w3lo[9 * 448 * 64];   // rows 432..447 stay zero

// ---------------- packed f32x2 helpers ----------------
__device__ __forceinline__ void fma2(ull& d, ull a, ull b) {
    asm("fma.rn.f32x2 %0, %1, %2, %0;" : "+l"(d) : "l"(a), "l"(b));
}
__device__ __forceinline__ ull pack2(float lo, float hi) {
    ull r; asm("mov.b64 %0, {%1, %2};" : "=l"(r) : "f"(lo), "f"(hi)); return r;
}
__device__ __forceinline__ void unpack2(ull p, float& lo, float& hi) {
    asm("mov.b64 {%0, %1}, %2;" : "=f"(lo), "=f"(hi) : "l"(p));
}

// ---------------- tf32 split ----------------
__device__ __forceinline__ void tsplit(float v, float& h, float& l) {
    uint32_t hb; asm("cvt.rna.tf32.f32 %0, %1;" : "=r"(hb) : "f"(v));
    h = __uint_as_float(hb);
    float r = v - h;
    uint32_t lb; asm("cvt.rna.tf32.f32 %0, %1;" : "=r"(lb) : "f"(r));
    l = __uint_as_float(lb);
}

// ---------------- warp mma m16n8k8 tf32 ----------------
__device__ __forceinline__ void mma8(float* c, const uint32_t* a, const uint32_t* b) {
    asm volatile(
        "mma.sync.aligned.m16n8k8.row.col.f32.tf32.tf32.f32 "
        "{%0,%1,%2,%3}, {%4,%5,%6,%7}, {%8,%9}, {%0,%1,%2,%3};"
        : "+f"(c[0]), "+f"(c[1]), "+f"(c[2]), "+f"(c[3])
        : "r"(a[0]), "r"(a[1]), "r"(a[2]), "r"(a[3]), "r"(b[0]), "r"(b[1]));
}

// ---------------- transpose x: NCHW -> N(HW)C ----------------
__global__ void transpose_x_kernel(const float* __restrict__ x, float* __restrict__ xt) {
    __shared__ float t[32][33];
    int b = blockIdx.z, y = blockIdx.y;
    int c0 = (blockIdx.x & 3) * 32;
    int w0 = (blockIdx.x >> 2) * 32;
    int tx = threadIdx.x, ty = threadIdx.y;
#pragma unroll
    for (int j = 0; j < 4; j++) {
        int c = c0 + ty + j * 8;
        t[ty + j * 8][tx] = x[((b * 128 + c) * HH + y) * WW + w0 + tx];
    }
    __syncthreads();
#pragma unroll
    for (int j = 0; j < 4; j++) {
        int w = w0 + ty + j * 8;
        xt[((size_t)b * HW + (size_t)y * WW + w) * 128 + c0 + tx] = t[tx][ty + j * 8];
    }
}

// ---------------- feat transform: concat(extra,flow1,flow2) -> padded NHWC hi/lo chunk-major ----------------
__global__ void prep_feat_kernel(
    const float* __restrict__ extra,
    const float* __restrict__ flow1,
    const float* __restrict__ flow2,
    float* __restrict__ fhi, float* __restrict__ flo)
{
    int b = blockIdx.z, y = blockIdx.y;
    int tx = threadIdx.x, ty = threadIdx.y;
    if (blockIdx.x < 18) {
        __shared__ float t[32][33];
        int wblk = blockIdx.x % 3, cg = blockIdx.x / 3;    // cg 0..5
        int w0 = wblk * 32;
#pragma unroll
        for (int j = 0; j < 4; j++) {
            int c = cg * 32 + ty + j * 8;
            t[ty + j * 8][tx] = extra[((size_t)(b * 192 + c)) * HW + y * WW + w0 + tx];
        }
        __syncthreads();
        int chunk = cg >> 1, coff = (cg & 1) * 32;
#pragma unroll
        for (int j = 0; j < 4; j++) {
            int w = w0 + ty + j * 8;
            int pixel = (y + 1) * 98 + (w + 1);
            float v = t[tx][ty + j * 8];
            float h, l;
            tsplit(v, h, l);
            size_t d = ((size_t)(chunk * BATCH + b) * PSTRIDE + PBASE + pixel) * 64 + coff + tx;
            fhi[d] = h;
            flo[d] = l;
        }
    } else {
        // flow channels -> chunk 3, coff 0..3
        int idx = ty * 32 + tx;
#pragma unroll
        for (int r = 0; r < 2; r++) {
            int ii = idx + 256 * r;
            if (ii < 384) {
                int w = ii % 96, cc = ii / 96;   // cc 0..3
                const float* src = (cc < 2 ? flow1 : flow2) + (size_t)(b * 2 + (cc & 1)) * HW;
                float v = src[y * WW + w];
                float h, l;
                tsplit(v, h, l);
                int pixel = (y + 1) * 98 + (w + 1);
                size_t d = ((size_t)(3 * BATCH + b) * PSTRIDE + PBASE + pixel) * 64 + cc;
                fhi[d] = h;
                flo[d] = l;
            }
        }
    }
}

// ---------------- deform-weight transpose ----------------
__global__ void prep_wd_kernel(const float* __restrict__ wgt, float* __restrict__ wd) {
    int i = blockIdx.x * 256 + threadIdx.x;
    int kk = i >> 6, o = i & 63;
    int g = kk / 72, r = kk - g * 72;
    int k = r >> 3, c = r & 7;
    wd[i] = wgt[(o * 128 + g * 8 + c) * 9 + k];
}

// ---------------- conv weight hi/lo split -> [tap][oc(OCP)][64ch] ----------------
__global__ void prep_wsplit_kernel(const float* __restrict__ src, float* __restrict__ hi,
                                   float* __restrict__ lo, int OC, int OCP) {
    int i = blockIdx.x * 256 + threadIdx.x;
    int n = 9 * OCP * 64;
    if (i >= n) return;
    int c = i & 63;
    int rest = i >> 6;
    int oc = rest % OCP;
    int tap = rest / OCP;
    if (oc >= OC) return;
    float w = src[((oc * 64 + c) * 3 + tap / 3) * 3 + (tap % 3)];
    float h, l;
    tsplit(w, h, l);
    hi[i] = h;
    lo[i] = l;
}

// ---------------- w0 split: ow0[oc][196][3][3] -> [chunk][tap][64oc][64ch] hi/lo ----------------
__global__ void prep_w0split_kernel(const float* __restrict__ src, float* __restrict__ hi,
                                    float* __restrict__ lo) {
    int i = blockIdx.x * 256 + threadIdx.x;
    if (i >= 4 * 9 * 64 * 64) return;
    int cc = i & 63;
    int rest = i >> 6;
    int oc = rest & 63;
    int rest2 = rest >> 6;
    int tap = rest2 % 9;
    int chunk = rest2 / 9;
    int c = chunk * 64 + cc;
    if (c >= 196) return;   // padded channels stay zero
    float w = src[((oc * 196 + c) * 3 + tap / 3) * 3 + (tap % 3)];
    float h, l;
    tsplit(w, h, l);
    hi[i] = h;
    lo[i] = l;
}

// ---------------- tensor conv via warp mma: 9-tap split-TF32 GEMM ----------------
// block 256 (8 warps); tile 128 px x 64 oc; warp = 32 px x 32 oc.
// NCHUNK k-chunks (A restaged per chunk, acc carried);
// NOCC oc-slices (A resident, B+epilogue per slice). Uses: NCHUNK>1 XOR NOCC>1.
#define APAD 68
#define ABYTES (326 * APAD * 4)
#define OFF_AL ABYTES
#define OFF_BH (2 * ABYTES)
#define OFF_BL (2 * ABYTES + 64 * APAD * 4)
#define TCM_SMEM (OFF_BL + 64 * APAD * 4)

template <int EPI, int OCP, int NCHUNK, int KS_LAST, int NOCC>
__global__ __launch_bounds__(256) void tconv_kernel(
    const float* __restrict__ inhi, const float* __restrict__ inlo,
    const float* __restrict__ wbhi, const float* __restrict__ wblo,
    const float* __restrict__ bias,
    float* __restrict__ outhi, float* __restrict__ outlo,
    float* __restrict__ offb, float* __restrict__ maskb,
    const float* __restrict__ flow1, const float* __restrict__ flow2)
{
    extern __shared__ __align__(16) char smem[];
    float* Ah = (float*)smem;
    float* Al = (float*)(smem + OFF_AL);
    float* Bh = (float*)(smem + OFF_BH);
    float* Bl = (float*)(smem + OFF_BL);

    const int tid = threadIdx.x;
    const int wid = tid >> 5, lane = tid & 31;
    const int gid = lane >> 2, tig = lane & 3;
    const int pxb = (wid & 3) * 32;
    const int ocb = (wid >> 2) * 32;
    const int b = blockIdx.z;
    const int p0 = blockIdx.x * 128;
    const size_t bb = (size_t)b * PSTRIDE + PBASE;
    const size_t ASTR = (size_t)BATCH * PSTRIDE * 64;   // chunk stride in A
    const int BSTR = 9 * OCP * 64;                      // chunk stride in B

    // B prefetch decomposition (constant per thread)
    int pfh[8], pfr[8], pfq[8];
#pragma unroll
    for (int i = 0; i < 8; i++) {
        int cc = tid + 256 * i;
        pfh[i] = cc >> 10;
        pfr[i] = (cc & 1023) >> 4;
        pfq[i] = cc & 15;
    }

#pragma unroll 1
    for (int os = 0; os < NOCC; os++) {
        const int occ = (NOCC > 1) ? os : blockIdx.y;

        float acc[2][4][4];
#pragma unroll
        for (int mt = 0; mt < 2; mt++)
#pragma unroll
            for (int nt = 0; nt < 4; nt++)
#pragma unroll
                for (int e = 0; e < 4; e++) acc[mt][nt][e] = 0.f;

#pragma unroll 1
        for (int ch = 0; ch < NCHUNK; ch++) {
            const bool first = (os == 0) && (ch == 0);
            if (!first) __syncthreads();   // all reads of previous A/B done

            const float* cAh = inhi + (size_t)ch * ASTR;
            const float* cAl = inlo + (size_t)ch * ASTR;
            const float* cBh = wbhi + (size_t)ch * BSTR;
            const float* cBl = wblo + (size_t)ch * BSTR;

            // ---- stage A window (only when data changes) ----
            if (NCHUNK > 1 || first) {
                const size_t rowbase = bb + p0 - 99;
#pragma unroll 1
                for (int i = 0; i < 41; i++) {
                    int cc = tid + 256 * i;
                    if (cc >= 10432) break;
                    int h = cc / 5216, rem = cc - h * 5216;
                    int r = rem >> 4, q = rem & 15;
                    float* dst = (h ? Al : Ah) + r * APAD + q * 4;
                    const float* src = (h ? cAl : cAh) + (rowbase + r) * 64 + q * 4;
                    __pipeline_memcpy_async(dst, src, 16);
                }
            }
            // ---- stage B tap 0 ----
            {
                const size_t brow = (size_t)occ * 64;
#pragma unroll
                for (int i = 0; i < 8; i++) {
                    int cc = tid + 256 * i;
                    int h = cc >> 10, rem = cc & 1023;
                    int r = rem >> 4, q = rem & 15;
                    float* dst = (h ? Bl : Bh) + r * APAD + q * 4;
                    const float* src = (h ? cBl : cBh) + (brow + r) * 64 + q * 4;
                    __pipeline_memcpy_async(dst, src, 16);
                }
            }
            __pipeline_commit();
            __pipeline_wait_prior(0);
            __syncthreads();

            const int KS = (ch == NCHUNK - 1) ? KS_LAST : 8;

#pragma unroll 1
            for (int tap = 0; tap < 9; tap++) {
                float4 pre[8];
                if (tap < 8) {
                    const size_t brow = (size_t)(tap + 1) * OCP + occ * 64;
#pragma unroll
                    for (int i = 0; i < 8; i++) {
                        const float* src = (pfh[i] ? cBl : cBh) + (brow + pfr[i]) * 64 + pfq[i] * 4;
                        pre[i] = *(const float4*)src;
                    }
                }

                const int shift = (tap / 3 - 1) * 98 + (tap % 3) - 1;
                const int abase0 = (pxb + gid + 99 + shift) * APAD + tig;

#pragma unroll
                for (int ks = 0; ks < 8; ks++) {
                    if (ks >= KS) break;
                    const int k = ks * 8;
                    uint32_t ahf[2][4], alf[2][4], bhf[4][2], blf[4][2];
#pragma unroll
                    for (int mt = 0; mt < 2; mt++) {
                        int base = abase0 + mt * 16 * APAD + k;
                        ahf[mt][0] = __float_as_uint(Ah[base]);
                        ahf[mt][1] = __float_as_uint(Ah[base + 8 * APAD]);
                        ahf[mt][2] = __float_as_uint(Ah[base + 4]);
                        ahf[mt][3] = __float_as_uint(Ah[base + 8 * APAD + 4]);
                        alf[mt][0] = __float_as_uint(Al[base]);
                        alf[mt][1] = __float_as_uint(Al[base + 8 * APAD]);
                        alf[mt][2] = __float_as_uint(Al[base + 4]);
                        alf[mt][3] = __float_as_uint(Al[base + 8 * APAD + 4]);
                    }
#pragma unroll
                    for (int nt = 0; nt < 4; nt++) {
                        int bbase = (ocb + nt * 8 + gid) * APAD + k + tig;
                        bhf[nt][0] = __float_as_uint(Bh[bbase]);
                        bhf[nt][1] = __float_as_uint(Bh[bbase + 4]);
                        blf[nt][0] = __float_as_uint(Bl[bbase]);
                        blf[nt][1] = __float_as_uint(Bl[bbase + 4]);
                    }
#pragma unroll
                    for (int mt = 0; mt < 2; mt++)
#pragma unroll
                        for (int nt = 0; nt < 4; nt++) {
                            mma8(acc[mt][nt], ahf[mt], bhf[nt]);
                            mma8(acc[mt][nt], ahf[mt], blf[nt]);
                            mma8(acc[mt][nt], alf[mt], bhf[nt]);
                        }
                }

                if (tap < 8) {
                    __syncthreads();
#pragma unroll
                    for (int i = 0; i < 8; i++) {
                        float* dst = (pfh[i] ? Bl : Bh) + pfr[i] * APAD + pfq[i] * 4;
                        *(float4*)dst = pre[i];
                    }
                    __syncthreads();
                }
            }
        }

        // ---- epilogue for this oc-slice ----
#pragma unroll
        for (int mt = 0; mt < 2; mt++) {
#pragma unroll
            for (int half = 0; half < 2; half++) {
                int pp = p0 + pxb + mt * 16 + gid + half * 8;
                int r98 = pp / 98, c98 = pp - r98 * 98;
                bool valid = (r98 >= 1) && (r98 <= 96) && (c98 >= 1) && (c98 <= 96);
                if (!valid) continue;
                if (EPI == 0) {
                    size_t ob = (bb + pp) * 64;
#pragma unroll
                    for (int nt = 0; nt < 4; nt++) {
                        int oc = ocb + nt * 8 + tig * 2;
                        float v0 = acc[mt][nt][half * 2 + 0] + __ldg(&bias[oc]);
                        float v1 = acc[mt][nt][half * 2 + 1] + __ldg(&bias[oc + 1]);
                        v0 = (v0 >= 0.f) ? v0 : 0.1f * v0;
                        v1 = (v1 >= 0.f) ? v1 : 0.1f * v1;
                        float h0, l0, h1, l1;
                        tsplit(v0, h0, l0);
                        tsplit(v1, h1, l1);
                        *(float2*)&outhi[ob + oc] = make_float2(h0, h1);
                        *(float2*)&outlo[ob + oc] = make_float2(l0, l1);
                    }
                } else {
                    int y = r98 - 1, x = c98 - 1;
                    int pix = y * WW + x;
                    float f1a = __ldg(&flow1[(size_t)(b * 2 + 0) * HW + pix]);
                    float f1b = __ldg(&flow1[(size_t)(b * 2 + 1) * HW + pix]);
                    float f2a = __ldg(&flow2[(size_t)(b * 2 + 0) * HW + pix]);
                    float f2b = __ldg(&flow2[(size_t)(b * 2 + 1) * HW + pix]);
#pragma unroll
                    for (int nt = 0; nt < 4; nt++) {
#pragma unroll
                        for (int e = 0; e < 2; e++) {
                            int oc = occ * 64 + ocb + nt * 8 + tig * 2 + e;
                            if (oc >= 432) continue;
                            float v = acc[mt][nt][half * 2 + e] + __ldg(&bias[oc]);
                            if (oc < 288) {
                                int par = 1 - (oc & 1);
                                float f = (oc < 144) ? (par ? f1b : f1a) : (par ? f2b : f2a);
                                offb[((size_t)b * 288 + oc) * HW + pix] = 10.f * tanhf(v) + f;
                            } else {
                                maskb[((size_t)b * 144 + (oc - 288)) * HW + pix] =
                                    1.f / (1.f + expf(-v));
                            }
                        }
                    }
                }
            }
        }
    }
}

// ---------------- deformable conv (unchanged) ----------------
#define SSTRIDE 1156

__global__ void deform_kernel(
    const float* __restrict__ xt,
    const float* __restrict__ off,
    const float* __restrict__ msk,
    const float* __restrict__ wd,
    const float* __restrict__ bias,
    float* __restrict__ out)
{
    extern __shared__ float s_sm[];
    int b = blockIdx.z;
    int h = blockIdx.y;
    int w0 = blockIdx.x * 16;
    int tid = threadIdx.x;
    {
        int px = tid & 15;
        int ww = w0 + px;
        int pospix = h * WW + ww;
        const float* offb = off + (size_t)b * 288 * HW + pospix;
        const float* mskb = msk + (size_t)b * 144 * HW + pospix;
        const float* xb = xt + (size_t)b * HW * 128;
#pragma unroll 1
        for (int it = 0; it < 9; it++) {
            int gk = (tid >> 4) + it * 16;
            int g = gk / 9, k = gk - g * 9;
            int ky = k / 3, kx = k - ky * 3;
            int oc = g * 18 + k * 2;
            float dy = offb[(size_t)oc * HW];
            float dx = offb[(size_t)(oc + 1) * HW];
            float m = mskb[(size_t)gk * HW];
            float py = dy + (float)(ky + h - 1);
            float pxx = dx + (float)(kx + ww - 1);
            float fy0 = floorf(py), fx0 = floorf(pxx);
            float wy1 = py - fy0, wx1 = pxx - fx0;
            int iy0 = (int)fy0, ix0 = (int)fx0;
            float a[8];
#pragma unroll
            for (int i = 0; i < 8; i++) a[i] = 0.f;
#pragma unroll
            for (int dyc = 0; dyc < 2; dyc++) {
#pragma unroll
                for (int dxc = 0; dxc < 2; dxc++) {
                    int yy = iy0 + dyc, xx = ix0 + dxc;
                    if ((unsigned)yy < HH && (unsigned)xx < WW) {
                        float wc = (dyc ? wy1 : 1.f - wy1) * (dxc ? wx1 : 1.f - wx1);
                        const float4* p = (const float4*)(xb + ((size_t)yy * WW + xx) * 128 + g * 8);
                        float4 v0 = p[0], v1 = p[1];
                        a[0] += wc * v0.x; a[1] += wc * v0.y; a[2] += wc * v0.z; a[3] += wc * v0.w;
                        a[4] += wc * v1.x; a[5] += wc * v1.y; a[6] += wc * v1.z; a[7] += wc * v1.w;
                    }
                }
            }
            float* sp = s_sm + px * SSTRIDE + g * 72 + k * 8;
            ((float4*)sp)[0] = make_float4(a[0] * m, a[1] * m, a[2] * m, a[3] * m);
            ((float4*)sp)[1] = make_float4(a[4] * m, a[5] * m, a[6] * m, a[7] * m);
        }
    }
    __syncthreads();
    {
        int og = tid & 15;
        int p2 = tid >> 4;
        const ulonglong2* wdv = (const ulonglong2*)wd;
        const float4* sr4 = (const float4*)(s_sm + p2 * SSTRIDE);
        float4 bbv = ((const float4*)bias)[og];
        ull a01 = pack2(bbv.x, bbv.y);
        ull a23 = pack2(bbv.z, bbv.w);
#pragma unroll 2
        for (int kk4 = 0; kk4 < 288; kk4++) {
            float4 sv = sr4[kk4];
            { ull ss = pack2(sv.x, sv.x); ulonglong2 wv = wdv[(kk4 * 4 + 0) * 16 + og];
              fma2(a01, wv.x, ss); fma2(a23, wv.y, ss); }
            { ull ss = pack2(sv.y, sv.y); ulonglong2 wv = wdv[(kk4 * 4 + 1) * 16 + og];
              fma2(a01, wv.x, ss); fma2(a23, wv.y, ss); }
            { ull ss = pack2(sv.z, sv.z); ulonglong2 wv = wdv[(kk4 * 4 + 2) * 16 + og];
              fma2(a01, wv.x, ss); fma2(a23, wv.y, ss); }
            { ull ss = pack2(sv.w, sv.w); ulonglong2 wv = wdv[(kk4 * 4 + 3) * 16 + og];
              fma2(a01, wv.x, ss); fma2(a23, wv.y, ss); }
        }
        float r0, r1, r2, r3;
        unpack2(a01, r0, r1);
        unpack2(a23, r2, r3);
        int oc = og * 4;
        size_t ob = (size_t)b * 64 * HW + (size_t)h * WW + w0 + p2;
        out[ob + (size_t)(oc + 0) * HW] = r0;
        out[ob + (size_t)(oc + 1) * HW] = r1;
        out[ob + (size_t)(oc + 2) * HW] = r2;
        out[ob + (size_t)(oc + 3) * HW] = r3;
    }
}

// ---------------- launch ----------------
extern "C" void kernel_launch(void* const* d_in, const int* in_sizes, int n_in,
                              void* d_out, int out_size)
{
    const float* x      = (const float*)d_in[0];
    const float* extra  = (const float*)d_in[1];
    const float* flow1  = (const float*)d_in[2];
    const float* flow2  = (const float*)d_in[3];
    const float* weight = (const float*)d_in[4];
    const float* bias   = (const float*)d_in[5];
    const float* ow0    = (const float*)d_in[6];
    const float* ob0    = (const float*)d_in[7];
    const float* ow1    = (const float*)d_in[8];
    const float* ob1    = (const float*)d_in[9];
    const float* ow2    = (const float*)d_in[10];
    const float* ob2    = (const float*)d_in[11];
    const float* ow3    = (const float*)d_in[12];
    const float* ob3    = (const float*)d_in[13];
    float* out = (float*)d_out;

    void *pahi, *palo, *pbhi, *pblo, *pfhi, *pflo, *poff, *pmask, *pxt, *pwd;
    void *pw0h, *pw0l, *pw1h, *pw1l, *pw2h, *pw2l, *pw3h, *pw3l;
    cudaGetSymbolAddress(&pahi, g_ha_hi);  cudaGetSymbolAddress(&palo, g_ha_lo);
    cudaGetSymbolAddress(&pbhi, g_hb_hi);  cudaGetSymbolAddress(&pblo, g_hb_lo);
    cudaGetSymbolAddress(&pfhi, g_ft_hi);  cudaGetSymbolAddress(&pflo, g_ft_lo);
    cudaGetSymbolAddress(&poff, g_off);    cudaGetSymbolAddress(&pmask, g_mask);
    cudaGetSymbolAddress(&pxt, g_xt);      cudaGetSymbolAddress(&pwd, g_wd);
    cudaGetSymbolAddress(&pw0h, g_w0hi);   cudaGetSymbolAddress(&pw0l, g_w0lo);
    cudaGetSymbolAddress(&pw1h, g_w1hi);   cudaGetSymbolAddress(&pw1l, g_w1lo);
    cudaGetSymbolAddress(&pw2h, g_w2hi);   cudaGetSymbolAddress(&pw2l, g_w2lo);
    cudaGetSymbolAddress(&pw3h, g_w3hi);   cudaGetSymbolAddress(&pw3l, g_w3lo);

    float *ahi = (float*)pahi, *alo = (float*)palo;
    float *bhi = (float*)pbhi, *blo = (float*)pblo;
    float *fhi = (float*)pfhi, *flo = (float*)pflo;
    float *offb = (float*)poff, *maskb = (float*)pmask;
    float *xtb = (float*)pxt, *wdb = (float*)pwd;

    transpose_x_kernel<<<dim3(12, 96, BATCH), dim3(32, 8)>>>(x, xtb);
    prep_wd_kernel<<<288, 256>>>(weight, wdb);
    prep_w0split_kernel<<<(4 * 9 * 64 * 64 + 255) / 256, 256>>>(ow0, (float*)pw0h, (float*)pw0l);
    prep_wsplit_kernel<<<(9 * 64 * 64 + 255) / 256, 256>>>(ow1, (float*)pw1h, (float*)pw1l, 64, 64);
    prep_wsplit_kernel<<<(9 * 64 * 64 + 255) / 256, 256>>>(ow2, (float*)pw2h, (float*)pw2l, 64, 64);
    prep_wsplit_kernel<<<(9 * 448 * 64 + 255) / 256, 256>>>(ow3, (float*)pw3h, (float*)pw3l, 432, 448);
    prep_feat_kernel<<<dim3(19, 96, BATCH), dim3(32, 8)>>>(extra, flow1, flow2, fhi, flo);

    cudaFuncSetAttribute(tconv_kernel<0, 64, 4, 1, 1>, cudaFuncAttributeMaxDynamicSharedMemorySize, TCM_SMEM);
    cudaFuncSetAttribute(tconv_kernel<0, 64, 1, 8, 1>, cudaFuncAttributeMaxDynamicSharedMemorySize, TCM_SMEM);
    cudaFuncSetAttribute(tconv_kernel<1, 448, 1, 8, 7>, cudaFuncAttributeMaxDynamicSharedMemorySize, TCM_SMEM);

    // conv0: feat -> ha   (4 K-chunks; last chunk 1 k-step)
    tconv_kernel<0, 64, 4, 1, 1><<<dim3(NTILE, 1, BATCH), 256, TCM_SMEM>>>(
        fhi, flo, (float*)pw0h, (float*)pw0l, ob0, ahi, alo,
        nullptr, nullptr, nullptr, nullptr);
    // conv1: ha -> hb
    tconv_kernel<0, 64, 1, 8, 1><<<dim3(NTILE, 1, BATCH), 256, TCM_SMEM>>>(
        ahi, alo, (float*)pw1h, (float*)pw1l, ob1, bhi, blo,
        nullptr, nullptr, nullptr, nullptr);
    // conv2: hb -> ha
    tconv_kernel<0, 64, 1, 8, 1><<<dim3(NTILE, 1, BATCH), 256, TCM_SMEM>>>(
        bhi, blo, (float*)pw2h, (float*)pw2l, ob2, ahi, alo,
        nullptr, nullptr, nullptr, nullptr);
    // conv3: ha -> offset/mask  (A resident, 7 oc-slices in-kernel)
    tconv_kernel<1, 448, 1, 8, 7><<<dim3(NTILE, 1, BATCH), 256, TCM_SMEM>>>(
        ahi, alo, (float*)pw3h, (float*)pw3l, ob3, nullptr, nullptr,
        offb, maskb, flow1, flow2);

    int smem = 16 * SSTRIDE * (int)sizeof(float);
    cudaFuncSetAttribute(deform_kernel, cudaFuncAttributeMaxDynamicSharedMemorySize, smem);
    deform_kernel<<<dim3(6, 96, BATCH), 256, smem>>>(xtb, offb, maskb, wdb, bias, out);
}

// round 16
// speedup vs baseline: 1.2200x; 1.0040x over previous
#include <cuda_runtime.h>
#include <cuda_pipeline.h>
#include <math.h>
#include <stdint.h>

#define HH 96
#define WW 96
#define HW 9216
#define BATCH 4
#define PSTRIDE 9984      // padded-NHWC pixels per batch image
#define PBASE 128         // front guard (>= 99)
#define NTILE 76          // 76 tiles of 128 padded pixels cover 98*98=9604

typedef unsigned long long ull;

// ---------------- scratch (static device globals; zero-initialized) ----------------
__device__ float g_ha_hi[BATCH * PSTRIDE * 64];
__device__ float g_ha_lo[BATCH * PSTRIDE * 64];
__device__ float g_hb_hi[BATCH * PSTRIDE * 64];
__device__ float g_hb_lo[BATCH * PSTRIDE * 64];
__device__ float g_ft_hi[4 * BATCH * PSTRIDE * 64];   // concat feat, chunk-major
__device__ float g_ft_lo[4 * BATCH * PSTRIDE * 64];
__device__ float g_off[BATCH * 288 * HW];
__device__ float g_mask[BATCH * 144 * HW];
__device__ float g_xt[BATCH * HW * 128];
__device__ float g_wd[1152 * 64];
__device__ float g_w0hi[4 * 9 * 64 * 64], g_w0lo[4 * 9 * 64 * 64];
__device__ float g_w1hi[9 * 64 * 64],  g_w1lo[9 * 64 * 64];
__device__ float g_w2hi[9 * 64 * 64],  g_w2lo[9 * 64 * 64];
__device__ float g_w3hi[9 * 448 * 64], g_w3lo[9 * 448 * 64];   // rows 432..447 stay zero

// ---------------- packed f32x2 helpers ----------------
__device__ __forceinline__ void fma2(ull& d, ull a, ull b) {
    asm("fma.rn.f32x2 %0, %1, %2, %0;" : "+l"(d) : "l"(a), "l"(b));
}
__device__ __forceinline__ ull pack2(float lo, float hi) {
    ull r; asm("mov.b64 %0, {%1, %2};" : "=l"(r) : "f"(lo), "f"(hi)); return r;
}
__device__ __forceinline__ void unpack2(ull p, float& lo, float& hi) {
    asm("mov.b64 {%0, %1}, %2;" : "=f"(lo), "=f"(hi) : "l"(p));
}

// ---------------- tf32 split ----------------
__device__ __forceinline__ void tsplit(float v, float& h, float& l) {
    uint32_t hb; asm("cvt.rna.tf32.f32 %0, %1;" : "=r"(hb) : "f"(v));
    h = __uint_as_float(hb);
    float r = v - h;
    uint32_t lb; asm("cvt.rna.tf32.f32 %0, %1;" : "=r"(lb) : "f"(r));
    l = __uint_as_float(lb);
}

// ---------------- warp mma m16n8k8 tf32 ----------------
__device__ __forceinline__ void mma8(float* c, const uint32_t* a, const uint32_t* b) {
    asm volatile(
        "mma.sync.aligned.m16n8k8.row.col.f32.tf32.tf32.f32 "
        "{%0,%1,%2,%3}, {%4,%5,%6,%7}, {%8,%9}, {%0,%1,%2,%3};"
        : "+f"(c[0]), "+f"(c[1]), "+f"(c[2]), "+f"(c[3])
        : "r"(a[0]), "r"(a[1]), "r"(a[2]), "r"(a[3]), "r"(b[0]), "r"(b[1]));
}

// ---------------- transpose x: NCHW -> N(HW)C ----------------
__global__ void transpose_x_kernel(const float* __restrict__ x, float* __restrict__ xt) {
    __shared__ float t[32][33];
    int b = blockIdx.z, y = blockIdx.y;
    int c0 = (blockIdx.x & 3) * 32;
    int w0 = (blockIdx.x >> 2) * 32;
    int tx = threadIdx.x, ty = threadIdx.y;
#pragma unroll
    for (int j = 0; j < 4; j++) {
        int c = c0 + ty + j * 8;
        t[ty + j * 8][tx] = x[((b * 128 + c) * HH + y) * WW + w0 + tx];
    }
    __syncthreads();
#pragma unroll
    for (int j = 0; j < 4; j++) {
        int w = w0 + ty + j * 8;
        xt[((size_t)b * HW + (size_t)y * WW + w) * 128 + c0 + tx] = t[tx][ty + j * 8];
    }
}

// ---------------- feat transform: concat(extra,flow1,flow2) -> padded NHWC hi/lo chunk-major ----------------
__global__ void prep_feat_kernel(
    const float* __restrict__ extra,
    const float* __restrict__ flow1,
    const float* __restrict__ flow2,
    float* __restrict__ fhi, float* __restrict__ flo)
{
    int b = blockIdx.z, y = blockIdx.y;
    int tx = threadIdx.x, ty = threadIdx.y;
    if (blockIdx.x < 18) {
        __shared__ float t[32][33];
        int wblk = blockIdx.x % 3, cg = blockIdx.x / 3;    // cg 0..5
        int w0 = wblk * 32;
#pragma unroll
        for (int j = 0; j < 4; j++) {
            int c = cg * 32 + ty + j * 8;
            t[ty + j * 8][tx] = extra[((size_t)(b * 192 + c)) * HW + y * WW + w0 + tx];
        }
        __syncthreads();
        int chunk = cg >> 1, coff = (cg & 1) * 32;
#pragma unroll
        for (int j = 0; j < 4; j++) {
            int w = w0 + ty + j * 8;
            int pixel = (y + 1) * 98 + (w + 1);
            float v = t[tx][ty + j * 8];
            float h, l;
            tsplit(v, h, l);
            size_t d = ((size_t)(chunk * BATCH + b) * PSTRIDE + PBASE + pixel) * 64 + coff + tx;
            fhi[d] = h;
            flo[d] = l;
        }
    } else {
        // flow channels -> chunk 3, coff 0..3
        int idx = ty * 32 + tx;
#pragma unroll
        for (int r = 0; r < 2; r++) {
            int ii = idx + 256 * r;
            if (ii < 384) {
                int w = ii % 96, cc = ii / 96;   // cc 0..3
                const float* src = (cc < 2 ? flow1 : flow2) + (size_t)(b * 2 + (cc & 1)) * HW;
                float v = src[y * WW + w];
                float h, l;
                tsplit(v, h, l);
                int pixel = (y + 1) * 98 + (w + 1);
                size_t d = ((size_t)(3 * BATCH + b) * PSTRIDE + PBASE + pixel) * 64 + cc;
                fhi[d] = h;
                flo[d] = l;
            }
        }
    }
}

// ---------------- deform-weight transpose ----------------
__global__ void prep_wd_kernel(const float* __restrict__ wgt, float* __restrict__ wd) {
    int i = blockIdx.x * 256 + threadIdx.x;
    int kk = i >> 6, o = i & 63;
    int g = kk / 72, r = kk - g * 72;
    int k = r >> 3, c = r & 7;
    wd[i] = wgt[(o * 128 + g * 8 + c) * 9 + k];
}

// ---------------- conv weight hi/lo split -> [tap][oc(OCP)][64ch] ----------------
__global__ void prep_wsplit_kernel(const float* __restrict__ src, float* __restrict__ hi,
                                   float* __restrict__ lo, int OC, int OCP) {
    int i = blockIdx.x * 256 + threadIdx.x;
    int n = 9 * OCP * 64;
    if (i >= n) return;
    int c = i & 63;
    int rest = i >> 6;
    int oc = rest % OCP;
    int tap = rest / OCP;
    if (oc >= OC) return;
    float w = src[((oc * 64 + c) * 3 + tap / 3) * 3 + (tap % 3)];
    float h, l;
    tsplit(w, h, l);
    hi[i] = h;
    lo[i] = l;
}

// ---------------- w0 split: ow0[oc][196][3][3] -> [chunk][tap][64oc][64ch] hi/lo ----------------
__global__ void prep_w0split_kernel(const float* __restrict__ src, float* __restrict__ hi,
                                    float* __restrict__ lo) {
    int i = blockIdx.x * 256 + threadIdx.x;
    if (i >= 4 * 9 * 64 * 64) return;
    int cc = i & 63;
    int rest = i >> 6;
    int oc = rest & 63;
    int rest2 = rest >> 6;
    int tap = rest2 % 9;
    int chunk = rest2 / 9;
    int c = chunk * 64 + cc;
    if (c >= 196) return;   // padded channels stay zero
    float w = src[((oc * 196 + c) * 3 + tap / 3) * 3 + (tap % 3)];
    float h, l;
    tsplit(w, h, l);
    hi[i] = h;
    lo[i] = l;
}

// ---------------- tensor conv via warp mma: 9-tap split-TF32 GEMM ----------------
// block 512 (16 warps, 4/SMSP); tile 128 px x 64 oc; warp = 32 px x 16 oc.
// NCHUNK k-chunks (A restaged per chunk, acc carried);
// NOCC oc-slices (A resident, B+epilogue per slice). Uses: NCHUNK>1 XOR NOCC>1.
#define APAD 68
#define ABYTES (326 * APAD * 4)
#define OFF_AL ABYTES
#define OFF_BH (2 * ABYTES)
#define OFF_BL (2 * ABYTES + 64 * APAD * 4)
#define TCM_SMEM (OFF_BL + 64 * APAD * 4)

template <int EPI, int OCP, int NCHUNK, int KS_LAST, int NOCC>
__global__ __launch_bounds__(512) void tconv_kernel(
    const float* __restrict__ inhi, const float* __restrict__ inlo,
    const float* __restrict__ wbhi, const float* __restrict__ wblo,
    const float* __restrict__ bias,
    float* __restrict__ outhi, float* __restrict__ outlo,
    float* __restrict__ offb, float* __restrict__ maskb,
    const float* __restrict__ flow1, const float* __restrict__ flow2)
{
    extern __shared__ __align__(16) char smem[];
    float* Ah = (float*)smem;
    float* Al = (float*)(smem + OFF_AL);
    float* Bh = (float*)(smem + OFF_BH);
    float* Bl = (float*)(smem + OFF_BL);

    const int tid = threadIdx.x;
    const int wid = tid >> 5, lane = tid & 31;
    const int gid = lane >> 2, tig = lane & 3;
    const int pxb = (wid & 3) * 32;        // warp pixel base (4 groups)
    const int ocb = (wid >> 2) * 16;       // warp oc base (4 groups of 16)
    const int b = blockIdx.z;
    const int p0 = blockIdx.x * 128;
    const size_t bb = (size_t)b * PSTRIDE + PBASE;
    const size_t ASTR = (size_t)BATCH * PSTRIDE * 64;   // chunk stride in A
    const int BSTR = 9 * OCP * 64;                      // chunk stride in B

    // B prefetch decomposition (constant per thread): 2048 16B copies over 512 threads
    int pfh[4], pfr[4], pfq[4];
#pragma unroll
    for (int i = 0; i < 4; i++) {
        int cc = tid + 512 * i;
        pfh[i] = cc >> 10;
        pfr[i] = (cc & 1023) >> 4;
        pfq[i] = cc & 15;
    }

#pragma unroll 1
    for (int os = 0; os < NOCC; os++) {
        const int occ = (NOCC > 1) ? os : blockIdx.y;

        float acc[2][2][4];
#pragma unroll
        for (int mt = 0; mt < 2; mt++)
#pragma unroll
            for (int nt = 0; nt < 2; nt++)
#pragma unroll
                for (int e = 0; e < 4; e++) acc[mt][nt][e] = 0.f;

#pragma unroll 1
        for (int ch = 0; ch < NCHUNK; ch++) {
            const bool first = (os == 0) && (ch == 0);
            if (!first) __syncthreads();   // all reads of previous A/B done

            const float* cAh = inhi + (size_t)ch * ASTR;
            const float* cAl = inlo + (size_t)ch * ASTR;
            const float* cBh = wbhi + (size_t)ch * BSTR;
            const float* cBl = wblo + (size_t)ch * BSTR;

            // ---- stage A window (only when data changes) ----
            if (NCHUNK > 1 || first) {
                const size_t rowbase = bb + p0 - 99;
#pragma unroll 1
                for (int i = 0; i < 21; i++) {
                    int cc = tid + 512 * i;
                    if (cc >= 10432) break;
                    int h = cc / 5216, rem = cc - h * 5216;
                    int r = rem >> 4, q = rem & 15;
                    float* dst = (h ? Al : Ah) + r * APAD + q * 4;
                    const float* src = (h ? cAl : cAh) + (rowbase + r) * 64 + q * 4;
                    __pipeline_memcpy_async(dst, src, 16);
                }
            }
            // ---- stage B tap 0 ----
            {
                const size_t brow = (size_t)occ * 64;
#pragma unroll
                for (int i = 0; i < 4; i++) {
                    int cc = tid + 512 * i;
                    int h = cc >> 10, rem = cc & 1023;
                    int r = rem >> 4, q = rem & 15;
                    float* dst = (h ? Bl : Bh) + r * APAD + q * 4;
                    const float* src = (h ? cBl : cBh) + (brow + r) * 64 + q * 4;
                    __pipeline_memcpy_async(dst, src, 16);
                }
            }
            __pipeline_commit();
            __pipeline_wait_prior(0);
            __syncthreads();

            const int KS = (ch == NCHUNK - 1) ? KS_LAST : 8;

#pragma unroll 1
            for (int tap = 0; tap < 9; tap++) {
                float4 pre[4];
                if (tap < 8) {
                    const size_t brow = (size_t)(tap + 1) * OCP + occ * 64;
#pragma unroll
                    for (int i = 0; i < 4; i++) {
                        const float* src = (pfh[i] ? cBl : cBh) + (brow + pfr[i]) * 64 + pfq[i] * 4;
                        pre[i] = *(const float4*)src;
                    }
                }

                const int shift = (tap / 3 - 1) * 98 + (tap % 3) - 1;
                const int abase0 = (pxb + gid + 99 + shift) * APAD + tig;

#pragma unroll
                for (int ks = 0; ks < 8; ks++) {
                    if (ks >= KS) break;
                    const int k = ks * 8;
                    uint32_t ahf[2][4], alf[2][4], bhf[2][2], blf[2][2];
#pragma unroll
                    for (int mt = 0; mt < 2; mt++) {
                        int base = abase0 + mt * 16 * APAD + k;
                        ahf[mt][0] = __float_as_uint(Ah[base]);
                        ahf[mt][1] = __float_as_uint(Ah[base + 8 * APAD]);
                        ahf[mt][2] = __float_as_uint(Ah[base + 4]);
                        ahf[mt][3] = __float_as_uint(Ah[base + 8 * APAD + 4]);
                        alf[mt][0] = __float_as_uint(Al[base]);
                        alf[mt][1] = __float_as_uint(Al[base + 8 * APAD]);
                        alf[mt][2] = __float_as_uint(Al[base + 4]);
                        alf[mt][3] = __float_as_uint(Al[base + 8 * APAD + 4]);
                    }
#pragma unroll
                    for (int nt = 0; nt < 2; nt++) {
                        int bbase = (ocb + nt * 8 + gid) * APAD + k + tig;
                        bhf[nt][0] = __float_as_uint(Bh[bbase]);
                        bhf[nt][1] = __float_as_uint(Bh[bbase + 4]);
                        blf[nt][0] = __float_as_uint(Bl[bbase]);
                        blf[nt][1] = __float_as_uint(Bl[bbase + 4]);
                    }
#pragma unroll
                    for (int mt = 0; mt < 2; mt++)
#pragma unroll
                        for (int nt = 0; nt < 2; nt++) {
                            mma8(acc[mt][nt], ahf[mt], bhf[nt]);
                            mma8(acc[mt][nt], ahf[mt], blf[nt]);
                            mma8(acc[mt][nt], alf[mt], bhf[nt]);
                        }
                }

                if (tap < 8) {
                    __syncthreads();
#pragma unroll
                    for (int i = 0; i < 4; i++) {
                        float* dst = (pfh[i] ? Bl : Bh) + pfr[i] * APAD + pfq[i] * 4;
                        *(float4*)dst = pre[i];
                    }
                    __syncthreads();
                }
            }
        }

        // ---- epilogue for this oc-slice ----
#pragma unroll
        for (int mt = 0; mt < 2; mt++) {
#pragma unroll
            for (int half = 0; half < 2; half++) {
                int pp = p0 + pxb + mt * 16 + gid + half * 8;
                int r98 = pp / 98, c98 = pp - r98 * 98;
                bool valid = (r98 >= 1) && (r98 <= 96) && (c98 >= 1) && (c98 <= 96);
                if (!valid) continue;
                if (EPI == 0) {
                    size_t ob = (bb + pp) * 64;
#pragma unroll
                    for (int nt = 0; nt < 2; nt++) {
                        int oc = ocb + nt * 8 + tig * 2;
                        float v0 = acc[mt][nt][half * 2 + 0] + __ldg(&bias[oc]);
                        float v1 = acc[mt][nt][half * 2 + 1] + __ldg(&bias[oc + 1]);
                        v0 = (v0 >= 0.f) ? v0 : 0.1f * v0;
                        v1 = (v1 >= 0.f) ? v1 : 0.1f * v1;
                        float h0, l0, h1, l1;
                        tsplit(v0, h0, l0);
                        tsplit(v1, h1, l1);
                        *(float2*)&outhi[ob + oc] = make_float2(h0, h1);
                        *(float2*)&outlo[ob + oc] = make_float2(l0, l1);
                    }
                } else {
                    int y = r98 - 1, x = c98 - 1;
                    int pix = y * WW + x;
                    float f1a = __ldg(&flow1[(size_t)(b * 2 + 0) * HW + pix]);
                    float f1b = __ldg(&flow1[(size_t)(b * 2 + 1) * HW + pix]);
                    float f2a = __ldg(&flow2[(size_t)(b * 2 + 0) * HW + pix]);
                    float f2b = __ldg(&flow2[(size_t)(b * 2 + 1) * HW + pix]);
#pragma unroll
                    for (int nt = 0; nt < 2; nt++) {
#pragma unroll
                        for (int e = 0; e < 2; e++) {
                            int oc = occ * 64 + ocb + nt * 8 + tig * 2 + e;
                            if (oc >= 432) continue;
                            float v = acc[mt][nt][half * 2 + e] + __ldg(&bias[oc]);
                            if (oc < 288) {
                                int par = 1 - (oc & 1);
                                float f = (oc < 144) ? (par ? f1b : f1a) : (par ? f2b : f2a);
                                offb[((size_t)b * 288 + oc) * HW + pix] = 10.f * tanhf(v) + f;
                            } else {
                                maskb[((size_t)b * 144 + (oc - 288)) * HW + pix] =
                                    1.f / (1.f + expf(-v));
                            }
                        }
                    }
                }
            }
        }
    }
}

// ---------------- deformable conv (unchanged) ----------------
#define SSTRIDE 1156

__global__ void deform_kernel(
    const float* __restrict__ xt,
    const float* __restrict__ off,
    const float* __restrict__ msk,
    const float* __restrict__ wd,
    const float* __restrict__ bias,
    float* __restrict__ out)
{
    extern __shared__ float s_sm[];
    int b = blockIdx.z;
    int h = blockIdx.y;
    int w0 = blockIdx.x * 16;
    int tid = threadIdx.x;
    {
        int px = tid & 15;
        int ww = w0 + px;
        int pospix = h * WW + ww;
        const float* offb = off + (size_t)b * 288 * HW + pospix;
        const float* mskb = msk + (size_t)b * 144 * HW + pospix;
        const float* xb = xt + (size_t)b * HW * 128;
#pragma unroll 1
        for (int it = 0; it < 9; it++) {
            int gk = (tid >> 4) + it * 16;
            int g = gk / 9, k = gk - g * 9;
            int ky = k / 3, kx = k - ky * 3;
            int oc = g * 18 + k * 2;
            float dy = offb[(size_t)oc * HW];
            float dx = offb[(size_t)(oc + 1) * HW];
            float m = mskb[(size_t)gk * HW];
            float py = dy + (float)(ky + h - 1);
            float pxx = dx + (float)(kx + ww - 1);
            float fy0 = floorf(py), fx0 = floorf(pxx);
            float wy1 = py - fy0, wx1 = pxx - fx0;
            int iy0 = (int)fy0, ix0 = (int)fx0;
            float a[8];
#pragma unroll
            for (int i = 0; i < 8; i++) a[i] = 0.f;
#pragma unroll
            for (int dyc = 0; dyc < 2; dyc++) {
#pragma unroll
                for (int dxc = 0; dxc < 2; dxc++) {
                    int yy = iy0 + dyc, xx = ix0 + dxc;
                    if ((unsigned)yy < HH && (unsigned)xx < WW) {
                        float wc = (dyc ? wy1 : 1.f - wy1) * (dxc ? wx1 : 1.f - wx1);
                        const float4* p = (const float4*)(xb + ((size_t)yy * WW + xx) * 128 + g * 8);
                        float4 v0 = p[0], v1 = p[1];
                        a[0] += wc * v0.x; a[1] += wc * v0.y; a[2] += wc * v0.z; a[3] += wc * v0.w;
                        a[4] += wc * v1.x; a[5] += wc * v1.y; a[6] += wc * v1.z; a[7] += wc * v1.w;
                    }
                }
            }
            float* sp = s_sm + px * SSTRIDE + g * 72 + k * 8;
            ((float4*)sp)[0] = make_float4(a[0] * m, a[1] * m, a[2] * m, a[3] * m);
            ((float4*)sp)[1] = make_float4(a[4] * m, a[5] * m, a[6] * m, a[7] * m);
        }
    }
    __syncthreads();
    {
        int og = tid & 15;
        int p2 = tid >> 4;
        const ulonglong2* wdv = (const ulonglong2*)wd;
        const float4* sr4 = (const float4*)(s_sm + p2 * SSTRIDE);
        float4 bbv = ((const float4*)bias)[og];
        ull a01 = pack2(bbv.x, bbv.y);
        ull a23 = pack2(bbv.z, bbv.w);
#pragma unroll 2
        for (int kk4 = 0; kk4 < 288; kk4++) {
            float4 sv = sr4[kk4];
            { ull ss = pack2(sv.x, sv.x); ulonglong2 wv = wdv[(kk4 * 4 + 0) * 16 + og];
              fma2(a01, wv.x, ss); fma2(a23, wv.y, ss); }
            { ull ss = pack2(sv.y, sv.y); ulonglong2 wv = wdv[(kk4 * 4 + 1) * 16 + og];
              fma2(a01, wv.x, ss); fma2(a23, wv.y, ss); }
            { ull ss = pack2(sv.z, sv.z); ulonglong2 wv = wdv[(kk4 * 4 + 2) * 16 + og];
              fma2(a01, wv.x, ss); fma2(a23, wv.y, ss); }
            { ull ss = pack2(sv.w, sv.w); ulonglong2 wv = wdv[(kk4 * 4 + 3) * 16 + og];
              fma2(a01, wv.x, ss); fma2(a23, wv.y, ss); }
        }
        float r0, r1, r2, r3;
        unpack2(a01, r0, r1);
        unpack2(a23, r2, r3);
        int oc = og * 4;
        size_t ob = (size_t)b * 64 * HW + (size_t)h * WW + w0 + p2;
        out[ob + (size_t)(oc + 0) * HW] = r0;
        out[ob + (size_t)(oc + 1) * HW] = r1;
        out[ob + (size_t)(oc + 2) * HW] = r2;
        out[ob + (size_t)(oc + 3) * HW] = r3;
    }
}

// ---------------- launch ----------------
extern "C" void kernel_launch(void* const* d_in, const int* in_sizes, int n_in,
                              void* d_out, int out_size)
{
    const float* x      = (const float*)d_in[0];
    const float* extra  = (const float*)d_in[1];
    const float* flow1  = (const float*)d_in[2];
    const float* flow2  = (const float*)d_in[3];
    const float* weight = (const float*)d_in[4];
    const float* bias   = (const float*)d_in[5];
    const float* ow0    = (const float*)d_in[6];
    const float* ob0    = (const float*)d_in[7];
    const float* ow1    = (const float*)d_in[8];
    const float* ob1    = (const float*)d_in[9];
    const float* ow2    = (const float*)d_in[10];
    const float* ob2    = (const float*)d_in[11];
    const float* ow3    = (const float*)d_in[12];
    const float* ob3    = (const float*)d_in[13];
    float* out = (float*)d_out;

    void *pahi, *palo, *pbhi, *pblo, *pfhi, *pflo, *poff, *pmask, *pxt, *pwd;
    void *pw0h, *pw0l, *pw1h, *pw1l, *pw2h, *pw2l, *pw3h, *pw3l;
    cudaGetSymbolAddress(&pahi, g_ha_hi);  cudaGetSymbolAddress(&palo, g_ha_lo);
    cudaGetSymbolAddress(&pbhi, g_hb_hi);  cudaGetSymbolAddress(&pblo, g_hb_lo);
    cudaGetSymbolAddress(&pfhi, g_ft_hi);  cudaGetSymbolAddress(&pflo, g_ft_lo);
    cudaGetSymbolAddress(&poff, g_off);    cudaGetSymbolAddress(&pmask, g_mask);
    cudaGetSymbolAddress(&pxt, g_xt);      cudaGetSymbolAddress(&pwd, g_wd);
    cudaGetSymbolAddress(&pw0h, g_w0hi);   cudaGetSymbolAddress(&pw0l, g_w0lo);
    cudaGetSymbolAddress(&pw1h, g_w1hi);   cudaGetSymbolAddress(&pw1l, g_w1lo);
    cudaGetSymbolAddress(&pw2h, g_w2hi);   cudaGetSymbolAddress(&pw2l, g_w2lo);
    cudaGetSymbolAddress(&pw3h, g_w3hi);   cudaGetSymbolAddress(&pw3l, g_w3lo);

    float *ahi = (float*)pahi, *alo = (float*)palo;
    float *bhi = (float*)pbhi, *blo = (float*)pblo;
    float *fhi = (float*)pfhi, *flo = (float*)pflo;
    float *offb = (float*)poff, *maskb = (float*)pmask;
    float *xtb = (float*)pxt, *wdb = (float*)pwd;

    transpose_x_kernel<<<dim3(12, 96, BATCH), dim3(32, 8)>>>(x, xtb);
    prep_wd_kernel<<<288, 256>>>(weight, wdb);
    prep_w0split_kernel<<<(4 * 9 * 64 * 64 + 255) / 256, 256>>>(ow0, (float*)pw0h, (float*)pw0l);
    prep_wsplit_kernel<<<(9 * 64 * 64 + 255) / 256, 256>>>(ow1, (float*)pw1h, (float*)pw1l, 64, 64);
    prep_wsplit_kernel<<<(9 * 64 * 64 + 255) / 256, 256>>>(ow2, (float*)pw2h, (float*)pw2l, 64, 64);
    prep_wsplit_kernel<<<(9 * 448 * 64 + 255) / 256, 256>>>(ow3, (float*)pw3h, (float*)pw3l, 432, 448);
    prep_feat_kernel<<<dim3(19, 96, BATCH), dim3(32, 8)>>>(extra, flow1, flow2, fhi, flo);

    cudaFuncSetAttribute(tconv_kernel<0, 64, 4, 1, 1>, cudaFuncAttributeMaxDynamicSharedMemorySize, TCM_SMEM);
    cudaFuncSetAttribute(tconv_kernel<0, 64, 1, 8, 1>, cudaFuncAttributeMaxDynamicSharedMemorySize, TCM_SMEM);
    cudaFuncSetAttribute(tconv_kernel<1, 448, 1, 8, 7>, cudaFuncAttributeMaxDynamicSharedMemorySize, TCM_SMEM);

    // conv0: feat -> ha   (4 K-chunks; last chunk 1 k-step)
    tconv_kernel<0, 64, 4, 1, 1><<<dim3(NTILE, 1, BATCH), 512, TCM_SMEM>>>(
        fhi, flo, (float*)pw0h, (float*)pw0l, ob0, ahi, alo,
        nullptr, nullptr, nullptr, nullptr);
    // conv1: ha -> hb
    tconv_kernel<0, 64, 1, 8, 1><<<dim3(NTILE, 1, BATCH), 512, TCM_SMEM>>>(
        ahi, alo, (float*)pw1h, (float*)pw1l, ob1, bhi, blo,
        nullptr, nullptr, nullptr, nullptr);
    // conv2: hb -> ha
    tconv_kernel<0, 64, 1, 8, 1><<<dim3(NTILE, 1, BATCH), 512, TCM_SMEM>>>(
        bhi, blo, (float*)pw2h, (float*)pw2l, ob2, ahi, alo,
        nullptr, nullptr, nullptr, nullptr);
    // conv3: ha -> offset/mask  (A resident, 7 oc-slices in-kernel)
    tconv_kernel<1, 448, 1, 8, 7><<<dim3(NTILE, 1, BATCH), 512, TCM_SMEM>>>(
        ahi, alo, (float*)pw3h, (float*)pw3l, ob3, nullptr, nullptr,
        offb, maskb, flow1, flow2);

    int smem = 16 * SSTRIDE * (int)sizeof(float);
    cudaFuncSetAttribute(deform_kernel, cudaFuncAttributeMaxDynamicSharedMemorySize, smem);
    deform_kernel<<<dim3(6, 96, BATCH), 256, smem>>>(xtb, offb, maskb, wdb, bias, out);
}

// round 17
// speedup vs baseline: 1.3492x; 1.1059x over previous
#include <cuda_runtime.h>
#include <cuda_pipeline.h>
#include <math.h>
#include <stdint.h>

#define HH 96
#define WW 96
#define HW 9216
#define BATCH 4
#define PSTRIDE 9984      // padded-NHWC pixels per batch image
#define PBASE 128         // front guard (>= 99)
#define NTILE 76          // 76 tiles of 128 padded pixels cover 98*98=9604

typedef unsigned long long ull;

// ---------------- scratch (static device globals; zero-initialized) ----------------
__device__ float g_ha_hi[BATCH * PSTRIDE * 64];
__device__ float g_ha_lo[BATCH * PSTRIDE * 64];
__device__ float g_hb_hi[BATCH * PSTRIDE * 64];
__device__ float g_hb_lo[BATCH * PSTRIDE * 64];
__device__ float g_ft_hi[4 * BATCH * PSTRIDE * 64];   // concat feat, chunk-major
__device__ float g_ft_lo[4 * BATCH * PSTRIDE * 64];
__device__ float g_off[BATCH * 288 * HW];
__device__ float g_mask[BATCH * 144 * HW];
__device__ float g_xt[BATCH * HW * 128];
__device__ float g_wd[1152 * 64];
__device__ float g_w0hi[4 * 9 * 64 * 64], g_w0lo[4 * 9 * 64 * 64];
__device__ float g_w1hi[9 * 64 * 64],  g_w1lo[9 * 64 * 64];
__device__ float g_w2hi[9 * 64 * 64],  g_w2lo[9 * 64 * 64];
__device__ float g_w3hi[9 * 448 * 64], g_w3lo[9 * 448 * 64];   // rows 432..447 stay zero

// ---------------- packed f32x2 helpers ----------------
__device__ __forceinline__ void fma2(ull& d, ull a, ull b) {
    asm("fma.rn.f32x2 %0, %1, %2, %0;" : "+l"(d) : "l"(a), "l"(b));
}
__device__ __forceinline__ ull pack2(float lo, float hi) {
    ull r; asm("mov.b64 %0, {%1, %2};" : "=l"(r) : "f"(lo), "f"(hi)); return r;
}
__device__ __forceinline__ void unpack2(ull p, float& lo, float& hi) {
    asm("mov.b64 {%0, %1}, %2;" : "=f"(lo), "=f"(hi) : "l"(p));
}

// ---------------- tf32 split ----------------
__device__ __forceinline__ void tsplit(float v, float& h, float& l) {
    uint32_t hb; asm("cvt.rna.tf32.f32 %0, %1;" : "=r"(hb) : "f"(v));
    h = __uint_as_float(hb);
    float r = v - h;
    uint32_t lb; asm("cvt.rna.tf32.f32 %0, %1;" : "=r"(lb) : "f"(r));
    l = __uint_as_float(lb);
}

// ---------------- warp mma m16n8k8 tf32 ----------------
__device__ __forceinline__ void mma8(float* c, const uint32_t* a, const uint32_t* b) {
    asm volatile(
        "mma.sync.aligned.m16n8k8.row.col.f32.tf32.tf32.f32 "
        "{%0,%1,%2,%3}, {%4,%5,%6,%7}, {%8,%9}, {%0,%1,%2,%3};"
        : "+f"(c[0]), "+f"(c[1]), "+f"(c[2]), "+f"(c[3])
        : "r"(a[0]), "r"(a[1]), "r"(a[2]), "r"(a[3]), "r"(b[0]), "r"(b[1]));
}

// ---------------- transpose x: NCHW -> N(HW)C ----------------
__global__ void transpose_x_kernel(const float* __restrict__ x, float* __restrict__ xt) {
    __shared__ float t[32][33];
    int b = blockIdx.z, y = blockIdx.y;
    int c0 = (blockIdx.x & 3) * 32;
    int w0 = (blockIdx.x >> 2) * 32;
    int tx = threadIdx.x, ty = threadIdx.y;
#pragma unroll
    for (int j = 0; j < 4; j++) {
        int c = c0 + ty + j * 8;
        t[ty + j * 8][tx] = x[((b * 128 + c) * HH + y) * WW + w0 + tx];
    }
    __syncthreads();
#pragma unroll
    for (int j = 0; j < 4; j++) {
        int w = w0 + ty + j * 8;
        xt[((size_t)b * HW + (size_t)y * WW + w) * 128 + c0 + tx] = t[tx][ty + j * 8];
    }
}

// ---------------- feat transform: concat(extra,flow1,flow2) -> padded NHWC hi/lo chunk-major ----------------
__global__ void prep_feat_kernel(
    const float* __restrict__ extra,
    const float* __restrict__ flow1,
    const float* __restrict__ flow2,
    float* __restrict__ fhi, float* __restrict__ flo)
{
    int b = blockIdx.z, y = blockIdx.y;
    int tx = threadIdx.x, ty = threadIdx.y;
    if (blockIdx.x < 18) {
        __shared__ float t[32][33];
        int wblk = blockIdx.x % 3, cg = blockIdx.x / 3;    // cg 0..5
        int w0 = wblk * 32;
#pragma unroll
        for (int j = 0; j < 4; j++) {
            int c = cg * 32 + ty + j * 8;
            t[ty + j * 8][tx] = extra[((size_t)(b * 192 + c)) * HW + y * WW + w0 + tx];
        }
        __syncthreads();
        int chunk = cg >> 1, coff = (cg & 1) * 32;
#pragma unroll
        for (int j = 0; j < 4; j++) {
            int w = w0 + ty + j * 8;
            int pixel = (y + 1) * 98 + (w + 1);
            float v = t[tx][ty + j * 8];
            float h, l;
            tsplit(v, h, l);
            size_t d = ((size_t)(chunk * BATCH + b) * PSTRIDE + PBASE + pixel) * 64 + coff + tx;
            fhi[d] = h;
            flo[d] = l;
        }
    } else {
        // flow channels -> chunk 3, coff 0..3
        int idx = ty * 32 + tx;
#pragma unroll
        for (int r = 0; r < 2; r++) {
            int ii = idx + 256 * r;
            if (ii < 384) {
                int w = ii % 96, cc = ii / 96;   // cc 0..3
                const float* src = (cc < 2 ? flow1 : flow2) + (size_t)(b * 2 + (cc & 1)) * HW;
                float v = src[y * WW + w];
                float h, l;
                tsplit(v, h, l);
                int pixel = (y + 1) * 98 + (w + 1);
                size_t d = ((size_t)(3 * BATCH + b) * PSTRIDE + PBASE + pixel) * 64 + cc;
                fhi[d] = h;
                flo[d] = l;
            }
        }
    }
}

// ---------------- deform-weight transpose ----------------
__global__ void prep_wd_kernel(const float* __restrict__ wgt, float* __restrict__ wd) {
    int i = blockIdx.x * 256 + threadIdx.x;
    int kk = i >> 6, o = i & 63;
    int g = kk / 72, r = kk - g * 72;
    int k = r >> 3, c = r & 7;
    wd[i] = wgt[(o * 128 + g * 8 + c) * 9 + k];
}

// ---------------- conv weight hi/lo split -> [tap][oc(OCP)][64ch] ----------------
__global__ void prep_wsplit_kernel(const float* __restrict__ src, float* __restrict__ hi,
                                   float* __restrict__ lo, int OC, int OCP) {
    int i = blockIdx.x * 256 + threadIdx.x;
    int n = 9 * OCP * 64;
    if (i >= n) return;
    int c = i & 63;
    int rest = i >> 6;
    int oc = rest % OCP;
    int tap = rest / OCP;
    if (oc >= OC) return;
    float w = src[((oc * 64 + c) * 3 + tap / 3) * 3 + (tap % 3)];
    float h, l;
    tsplit(w, h, l);
    hi[i] = h;
    lo[i] = l;
}

// ---------------- w0 split: ow0[oc][196][3][3] -> [chunk][tap][64oc][64ch] hi/lo ----------------
__global__ void prep_w0split_kernel(const float* __restrict__ src, float* __restrict__ hi,
                                    float* __restrict__ lo) {
    int i = blockIdx.x * 256 + threadIdx.x;
    if (i >= 4 * 9 * 64 * 64) return;
    int cc = i & 63;
    int rest = i >> 6;
    int oc = rest & 63;
    int rest2 = rest >> 6;
    int tap = rest2 % 9;
    int chunk = rest2 / 9;
    int c = chunk * 64 + cc;
    if (c >= 196) return;   // padded channels stay zero
    float w = src[((oc * 196 + c) * 3 + tap / 3) * 3 + (tap % 3)];
    float h, l;
    tsplit(w, h, l);
    hi[i] = h;
    lo[i] = l;
}

// ---------------- tensor conv via warp mma: 9-tap split-TF32 GEMM ----------------
// block 512 (16 warps, 4/SMSP); tile 128 px x 64 oc; warp = 32 px x 16 oc.
// NCHUNK k-chunks (A restaged per chunk, acc carried);
// NOCC oc-slices per block (A resident); grid.y partitions slice groups.
#define APAD 68
#define ABYTES (326 * APAD * 4)
#define OFF_AL ABYTES
#define OFF_BH (2 * ABYTES)
#define OFF_BL (2 * ABYTES + 64 * APAD * 4)
#define TCM_SMEM (OFF_BL + 64 * APAD * 4)

template <int EPI, int OCP, int NCHUNK, int KS_LAST, int NOCC>
__global__ __launch_bounds__(512) void tconv_kernel(
    const float* __restrict__ inhi, const float* __restrict__ inlo,
    const float* __restrict__ wbhi, const float* __restrict__ wblo,
    const float* __restrict__ bias,
    float* __restrict__ outhi, float* __restrict__ outlo,
    float* __restrict__ offb, float* __restrict__ maskb,
    const float* __restrict__ flow1, const float* __restrict__ flow2)
{
    extern __shared__ __align__(16) char smem[];
    float* Ah = (float*)smem;
    float* Al = (float*)(smem + OFF_AL);
    float* Bh = (float*)(smem + OFF_BH);
    float* Bl = (float*)(smem + OFF_BL);

    const int tid = threadIdx.x;
    const int wid = tid >> 5, lane = tid & 31;
    const int gid = lane >> 2, tig = lane & 3;
    const int pxb = (wid & 3) * 32;        // warp pixel base (4 groups)
    const int ocb = (wid >> 2) * 16;       // warp oc base (4 groups of 16)
    const int b = blockIdx.z;
    const int p0 = blockIdx.x * 128;
    const size_t bb = (size_t)b * PSTRIDE + PBASE;
    const size_t ASTR = (size_t)BATCH * PSTRIDE * 64;   // chunk stride in A
    const int BSTR = 9 * OCP * 64;                      // chunk stride in B

    // B prefetch decomposition (constant per thread): 2048 16B copies over 512 threads
    int pfh[4], pfr[4], pfq[4];
#pragma unroll
    for (int i = 0; i < 4; i++) {
        int cc = tid + 512 * i;
        pfh[i] = cc >> 10;
        pfr[i] = (cc & 1023) >> 4;
        pfq[i] = cc & 15;
    }

#pragma unroll 1
    for (int os = 0; os < NOCC; os++) {
        const int occ = (NOCC > 1) ? (blockIdx.y * NOCC + os) : blockIdx.y;
        if (NOCC > 1 && occ >= OCP / 64) break;

        float acc[2][2][4];
#pragma unroll
        for (int mt = 0; mt < 2; mt++)
#pragma unroll
            for (int nt = 0; nt < 2; nt++)
#pragma unroll
                for (int e = 0; e < 4; e++) acc[mt][nt][e] = 0.f;

#pragma unroll 1
        for (int ch = 0; ch < NCHUNK; ch++) {
            const bool first = (os == 0) && (ch == 0);
            if (!first) __syncthreads();   // all reads of previous A/B done

            const float* cAh = inhi + (size_t)ch * ASTR;
            const float* cAl = inlo + (size_t)ch * ASTR;
            const float* cBh = wbhi + (size_t)ch * BSTR;
            const float* cBl = wblo + (size_t)ch * BSTR;

            // ---- stage A window (only when data changes) ----
            if (NCHUNK > 1 || first) {
                const size_t rowbase = bb + p0 - 99;
#pragma unroll 1
                for (int i = 0; i < 21; i++) {
                    int cc = tid + 512 * i;
                    if (cc >= 10432) break;
                    int h = cc / 5216, rem = cc - h * 5216;
                    int r = rem >> 4, q = rem & 15;
                    float* dst = (h ? Al : Ah) + r * APAD + q * 4;
                    const float* src = (h ? cAl : cAh) + (rowbase + r) * 64 + q * 4;
                    __pipeline_memcpy_async(dst, src, 16);
                }
            }
            // ---- stage B tap 0 ----
            {
                const size_t brow = (size_t)occ * 64;
#pragma unroll
                for (int i = 0; i < 4; i++) {
                    int cc = tid + 512 * i;
                    int h = cc >> 10, rem = cc & 1023;
                    int r = rem >> 4, q = rem & 15;
                    float* dst = (h ? Bl : Bh) + r * APAD + q * 4;
                    const float* src = (h ? cBl : cBh) + (brow + r) * 64 + q * 4;
                    __pipeline_memcpy_async(dst, src, 16);
                }
            }
            __pipeline_commit();
            __pipeline_wait_prior(0);
            __syncthreads();

            const int KS = (ch == NCHUNK - 1) ? KS_LAST : 8;

#pragma unroll 1
            for (int tap = 0; tap < 9; tap++) {
                float4 pre[4];
                if (tap < 8) {
                    const size_t brow = (size_t)(tap + 1) * OCP + occ * 64;
#pragma unroll
                    for (int i = 0; i < 4; i++) {
                        const float* src = (pfh[i] ? cBl : cBh) + (brow + pfr[i]) * 64 + pfq[i] * 4;
                        pre[i] = *(const float4*)src;
                    }
                }

                const int shift = (tap / 3 - 1) * 98 + (tap % 3) - 1;
                const int abase0 = (pxb + gid + 99 + shift) * APAD + tig;

#pragma unroll
                for (int ks = 0; ks < 8; ks++) {
                    if (ks >= KS) break;
                    const int k = ks * 8;
                    uint32_t ahf[2][4], alf[2][4], bhf[2][2], blf[2][2];
#pragma unroll
                    for (int mt = 0; mt < 2; mt++) {
                        int base = abase0 + mt * 16 * APAD + k;
                        ahf[mt][0] = __float_as_uint(Ah[base]);
                        ahf[mt][1] = __float_as_uint(Ah[base + 8 * APAD]);
                        ahf[mt][2] = __float_as_uint(Ah[base + 4]);
                        ahf[mt][3] = __float_as_uint(Ah[base + 8 * APAD + 4]);
                        alf[mt][0] = __float_as_uint(Al[base]);
                        alf[mt][1] = __float_as_uint(Al[base + 8 * APAD]);
                        alf[mt][2] = __float_as_uint(Al[base + 4]);
                        alf[mt][3] = __float_as_uint(Al[base + 8 * APAD + 4]);
                    }
#pragma unroll
                    for (int nt = 0; nt < 2; nt++) {
                        int bbase = (ocb + nt * 8 + gid) * APAD + k + tig;
                        bhf[nt][0] = __float_as_uint(Bh[bbase]);
                        bhf[nt][1] = __float_as_uint(Bh[bbase + 4]);
                        blf[nt][0] = __float_as_uint(Bl[bbase]);
                        blf[nt][1] = __float_as_uint(Bl[bbase + 4]);
                    }
#pragma unroll
                    for (int mt = 0; mt < 2; mt++)
#pragma unroll
                        for (int nt = 0; nt < 2; nt++) {
                            mma8(acc[mt][nt], ahf[mt], bhf[nt]);
                            mma8(acc[mt][nt], ahf[mt], blf[nt]);
                            mma8(acc[mt][nt], alf[mt], bhf[nt]);
                        }
                }

                if (tap < 8) {
                    __syncthreads();
#pragma unroll
                    for (int i = 0; i < 4; i++) {
                        float* dst = (pfh[i] ? Bl : Bh) + pfr[i] * APAD + pfq[i] * 4;
                        *(float4*)dst = pre[i];
                    }
                    __syncthreads();
                }
            }
        }

        // ---- epilogue for this oc-slice ----
#pragma unroll
        for (int mt = 0; mt < 2; mt++) {
#pragma unroll
            for (int half = 0; half < 2; half++) {
                int pp = p0 + pxb + mt * 16 + gid + half * 8;
                int r98 = pp / 98, c98 = pp - r98 * 98;
                bool valid = (r98 >= 1) && (r98 <= 96) && (c98 >= 1) && (c98 <= 96);
                if (!valid) continue;
                if (EPI == 0) {
                    size_t ob = (bb + pp) * 64;
#pragma unroll
                    for (int nt = 0; nt < 2; nt++) {
                        int oc = ocb + nt * 8 + tig * 2;
                        float v0 = acc[mt][nt][half * 2 + 0] + __ldg(&bias[oc]);
                        float v1 = acc[mt][nt][half * 2 + 1] + __ldg(&bias[oc + 1]);
                        v0 = (v0 >= 0.f) ? v0 : 0.1f * v0;
                        v1 = (v1 >= 0.f) ? v1 : 0.1f * v1;
                        float h0, l0, h1, l1;
                        tsplit(v0, h0, l0);
                        tsplit(v1, h1, l1);
                        *(float2*)&outhi[ob + oc] = make_float2(h0, h1);
                        *(float2*)&outlo[ob + oc] = make_float2(l0, l1);
                    }
                } else {
                    int y = r98 - 1, x = c98 - 1;
                    int pix = y * WW + x;
                    float f1a = __ldg(&flow1[(size_t)(b * 2 + 0) * HW + pix]);
                    float f1b = __ldg(&flow1[(size_t)(b * 2 + 1) * HW + pix]);
                    float f2a = __ldg(&flow2[(size_t)(b * 2 + 0) * HW + pix]);
                    float f2b = __ldg(&flow2[(size_t)(b * 2 + 1) * HW + pix]);
#pragma unroll
                    for (int nt = 0; nt < 2; nt++) {
#pragma unroll
                        for (int e = 0; e < 2; e++) {
                            int oc = occ * 64 + ocb + nt * 8 + tig * 2 + e;
                            if (oc >= 432) continue;
                            float v = acc[mt][nt][half * 2 + e] + __ldg(&bias[oc]);
                            if (oc < 288) {
                                int par = 1 - (oc & 1);
                                float f = (oc < 144) ? (par ? f1b : f1a) : (par ? f2b : f2a);
                                offb[((size_t)b * 288 + oc) * HW + pix] = 10.f * tanhf(v) + f;
                            } else {
                                maskb[((size_t)b * 144 + (oc - 288)) * HW + pix] =
                                    1.f / (1.f + expf(-v));
                            }
                        }
                    }
                }
            }
        }
    }
}

// ---------------- deformable conv: gather + split-K GEMM ----------------
#define SSTRIDE 1156

__global__ void deform_kernel(
    const float* __restrict__ xt,
    const float* __restrict__ off,
    const float* __restrict__ msk,
    const float* __restrict__ wd,
    const float* __restrict__ bias,
    float* __restrict__ out)
{
    extern __shared__ float s_sm[];
    int b = blockIdx.z;
    int h = blockIdx.y;
    int w0 = blockIdx.x * 16;
    int tid = threadIdx.x;

    // ---------- phase 1: bilinear gather into smem ----------
    {
        int px = tid & 15;
        int ww = w0 + px;
        int pospix = h * WW + ww;
        const float* offb = off + (size_t)b * 288 * HW + pospix;
        const float* mskb = msk + (size_t)b * 144 * HW + pospix;
        const float* xb = xt + (size_t)b * HW * 128;
#pragma unroll 1
        for (int it = 0; it < 9; it++) {
            int gk = (tid >> 4) + it * 16;
            int g = gk / 9, k = gk - g * 9;
            int ky = k / 3, kx = k - ky * 3;
            int oc = g * 18 + k * 2;
            float dy = offb[(size_t)oc * HW];
            float dx = offb[(size_t)(oc + 1) * HW];
            float m = mskb[(size_t)gk * HW];
            float py = dy + (float)(ky + h - 1);
            float pxx = dx + (float)(kx + ww - 1);
            float fy0 = floorf(py), fx0 = floorf(pxx);
            float wy1 = py - fy0, wx1 = pxx - fx0;
            int iy0 = (int)fy0, ix0 = (int)fx0;
            float a[8];
#pragma unroll
            for (int i = 0; i < 8; i++) a[i] = 0.f;
#pragma unroll
            for (int dyc = 0; dyc < 2; dyc++) {
#pragma unroll
                for (int dxc = 0; dxc < 2; dxc++) {
                    int yy = iy0 + dyc, xx = ix0 + dxc;
                    if ((unsigned)yy < HH && (unsigned)xx < WW) {
                        float wc = (dyc ? wy1 : 1.f - wy1) * (dxc ? wx1 : 1.f - wx1);
                        const float4* p = (const float4*)(xb + ((size_t)yy * WW + xx) * 128 + g * 8);
                        float4 v0 = p[0], v1 = p[1];
                        a[0] += wc * v0.x; a[1] += wc * v0.y; a[2] += wc * v0.z; a[3] += wc * v0.w;
                        a[4] += wc * v1.x; a[5] += wc * v1.y; a[6] += wc * v1.z; a[7] += wc * v1.w;
                    }
                }
            }
            float* sp = s_sm + px * SSTRIDE + g * 72 + k * 8;
            ((float4*)sp)[0] = make_float4(a[0] * m, a[1] * m, a[2] * m, a[3] * m);
            ((float4*)sp)[1] = make_float4(a[4] * m, a[5] * m, a[6] * m, a[7] * m);
        }
    }
    __syncthreads();

    // ---------- phase 2: split-K GEMM, each thread 2 px x 4 oc x half-K ----------
    {
        int og = tid & 15;               // 4 output channels: og*4..og*4+3
        int pg = (tid >> 4) & 7;         // pixel pair
        int ks = tid >> 7;               // K half (0 or 1)
        int p = pg * 2;
        const ulonglong2* wdv = (const ulonglong2*)wd;
        const float4* sr0 = (const float4*)(s_sm + p * SSTRIDE);
        const float4* sr1 = (const float4*)(s_sm + (p + 1) * SSTRIDE);
        ull a01_0 = 0, a23_0 = 0, a01_1 = 0, a23_1 = 0;
        const int kbase = ks * 144;      // float4 index base (576 kk / 4)

#pragma unroll 2
        for (int k4 = 0; k4 < 144; k4++) {
            float4 s0 = sr0[kbase + k4];
            float4 s1 = sr1[kbase + k4];
            int kk = (kbase + k4) * 4;
            {
                ulonglong2 wv = wdv[(kk + 0) * 16 + og];
                ull t0 = pack2(s0.x, s0.x), t1 = pack2(s1.x, s1.x);
                fma2(a01_0, wv.x, t0); fma2(a23_0, wv.y, t0);
                fma2(a01_1, wv.x, t1); fma2(a23_1, wv.y, t1);
            }
            {
                ulonglong2 wv = wdv[(kk + 1) * 16 + og];
                ull t0 = pack2(s0.y, s0.y), t1 = pack2(s1.y, s1.y);
                fma2(a01_0, wv.x, t0); fma2(a23_0, wv.y, t0);
                fma2(a01_1, wv.x, t1); fma2(a23_1, wv.y, t1);
            }
            {
                ulonglong2 wv = wdv[(kk + 2) * 16 + og];
                ull t0 = pack2(s0.z, s0.z), t1 = pack2(s1.z, s1.z);
                fma2(a01_0, wv.x, t0); fma2(a23_0, wv.y, t0);
                fma2(a01_1, wv.x, t1); fma2(a23_1, wv.y, t1);
            }
            {
                ulonglong2 wv = wdv[(kk + 3) * 16 + og];
                ull t0 = pack2(s0.w, s0.w), t1 = pack2(s1.w, s1.w);
                fma2(a01_0, wv.x, t0); fma2(a23_0, wv.y, t0);
                fma2(a01_1, wv.x, t1); fma2(a23_1, wv.y, t1);
            }
        }

        __syncthreads();   // all s_sm sample reads done
        if (ks == 1) {
            float r0, r1, r2, r3, q0, q1, q2, q3;
            unpack2(a01_0, r0, r1); unpack2(a23_0, r2, r3);
            unpack2(a01_1, q0, q1); unpack2(a23_1, q2, q3);
            *(float4*)&s_sm[p * 64 + og * 4] = make_float4(r0, r1, r2, r3);
            *(float4*)&s_sm[(p + 1) * 64 + og * 4] = make_float4(q0, q1, q2, q3);
        }
        __syncthreads();
        if (ks == 0) {
            float4 bb4 = ((const float4*)bias)[og];
            float4 o0 = *(const float4*)&s_sm[p * 64 + og * 4];
            float4 o1 = *(const float4*)&s_sm[(p + 1) * 64 + og * 4];
            float r0, r1, r2, r3, q0, q1, q2, q3;
            unpack2(a01_0, r0, r1); unpack2(a23_0, r2, r3);
            unpack2(a01_1, q0, q1); unpack2(a23_1, q2, q3);
            int oc = og * 4;
            size_t ob0 = (size_t)b * 64 * HW + (size_t)h * WW + w0 + p;
            out[ob0 + (size_t)(oc + 0) * HW] = r0 + o0.x + bb4.x;
            out[ob0 + (size_t)(oc + 1) * HW] = r1 + o0.y + bb4.y;
            out[ob0 + (size_t)(oc + 2) * HW] = r2 + o0.z + bb4.z;
            out[ob0 + (size_t)(oc + 3) * HW] = r3 + o0.w + bb4.w;
            size_t ob1 = ob0 + 1;
            out[ob1 + (size_t)(oc + 0) * HW] = q0 + o1.x + bb4.x;
            out[ob1 + (size_t)(oc + 1) * HW] = q1 + o1.y + bb4.y;
            out[ob1 + (size_t)(oc + 2) * HW] = q2 + o1.z + bb4.z;
            out[ob1 + (size_t)(oc + 3) * HW] = q3 + o1.w + bb4.w;
        }
    }
}

// ---------------- launch ----------------
extern "C" void kernel_launch(void* const* d_in, const int* in_sizes, int n_in,
                              void* d_out, int out_size)
{
    const float* x      = (const float*)d_in[0];
    const float* extra  = (const float*)d_in[1];
    const float* flow1  = (const float*)d_in[2];
    const float* flow2  = (const float*)d_in[3];
    const float* weight = (const float*)d_in[4];
    const float* bias   = (const float*)d_in[5];
    const float* ow0    = (const float*)d_in[6];
    const float* ob0    = (const float*)d_in[7];
    const float* ow1    = (const float*)d_in[8];
    const float* ob1    = (const float*)d_in[9];
    const float* ow2    = (const float*)d_in[10];
    const float* ob2    = (const float*)d_in[11];
    const float* ow3    = (const float*)d_in[12];
    const float* ob3    = (const float*)d_in[13];
    float* out = (float*)d_out;

    void *pahi, *palo, *pbhi, *pblo, *pfhi, *pflo, *poff, *pmask, *pxt, *pwd;
    void *pw0h, *pw0l, *pw1h, *pw1l, *pw2h, *pw2l, *pw3h, *pw3l;
    cudaGetSymbolAddress(&pahi, g_ha_hi);  cudaGetSymbolAddress(&palo, g_ha_lo);
    cudaGetSymbolAddress(&pbhi, g_hb_hi);  cudaGetSymbolAddress(&pblo, g_hb_lo);
    cudaGetSymbolAddress(&pfhi, g_ft_hi);  cudaGetSymbolAddress(&pflo, g_ft_lo);
    cudaGetSymbolAddress(&poff, g_off);    cudaGetSymbolAddress(&pmask, g_mask);
    cudaGetSymbolAddress(&pxt, g_xt);      cudaGetSymbolAddress(&pwd, g_wd);
    cudaGetSymbolAddress(&pw0h, g_w0hi);   cudaGetSymbolAddress(&pw0l, g_w0lo);
    cudaGetSymbolAddress(&pw1h, g_w1hi);   cudaGetSymbolAddress(&pw1l, g_w1lo);
    cudaGetSymbolAddress(&pw2h, g_w2hi);   cudaGetSymbolAddress(&pw2l, g_w2lo);
    cudaGetSymbolAddress(&pw3h, g_w3hi);   cudaGetSymbolAddress(&pw3l, g_w3lo);

    float *ahi = (float*)pahi, *alo = (float*)palo;
    float *bhi = (float*)pbhi, *blo = (float*)pblo;
    float *fhi = (float*)pfhi, *flo = (float*)pflo;
    float *offb = (float*)poff, *maskb = (float*)pmask;
    float *xtb = (float*)pxt, *wdb = (float*)pwd;

    transpose_x_kernel<<<dim3(12, 96, BATCH), dim3(32, 8)>>>(x, xtb);
    prep_wd_kernel<<<288, 256>>>(weight, wdb);
    prep_w0split_kernel<<<(4 * 9 * 64 * 64 + 255) / 256, 256>>>(ow0, (float*)pw0h, (float*)pw0l);
    prep_wsplit_kernel<<<(9 * 64 * 64 + 255) / 256, 256>>>(ow1, (float*)pw1h, (float*)pw1l, 64, 64);
    prep_wsplit_kernel<<<(9 * 64 * 64 + 255) / 256, 256>>>(ow2, (float*)pw2h, (float*)pw2l, 64, 64);
    prep_wsplit_kernel<<<(9 * 448 * 64 + 255) / 256, 256>>>(ow3, (float*)pw3h, (float*)pw3l, 432, 448);
    prep_feat_kernel<<<dim3(19, 96, BATCH), dim3(32, 8)>>>(extra, flow1, flow2, fhi, flo);

    cudaFuncSetAttribute(tconv_kernel<0, 64, 4, 1, 1>, cudaFuncAttributeMaxDynamicSharedMemorySize, TCM_SMEM);
    cudaFuncSetAttribute(tconv_kernel<0, 64, 1, 8, 1>, cudaFuncAttributeMaxDynamicSharedMemorySize, TCM_SMEM);
    cudaFuncSetAttribute(tconv_kernel<1, 448, 1, 8, 4>, cudaFuncAttributeMaxDynamicSharedMemorySize, TCM_SMEM);

    // conv0: feat -> ha   (4 K-chunks; last chunk 1 k-step)
    tconv_kernel<0, 64, 4, 1, 1><<<dim3(NTILE, 1, BATCH), 512, TCM_SMEM>>>(
        fhi, flo, (float*)pw0h, (float*)pw0l, ob0, ahi, alo,
        nullptr, nullptr, nullptr, nullptr);
    // conv1: ha -> hb
    tconv_kernel<0, 64, 1, 8, 1><<<dim3(NTILE, 1, BATCH), 512, TCM_SMEM>>>(
        ahi, alo, (float*)pw1h, (float*)pw1l, ob1, bhi, blo,
        nullptr, nullptr, nullptr, nullptr);
    // conv2: hb -> ha
    tconv_kernel<0, 64, 1, 8, 1><<<dim3(NTILE, 1, BATCH), 512, TCM_SMEM>>>(
        bhi, blo, (float*)pw2h, (float*)pw2l, ob2, ahi, alo,
        nullptr, nullptr, nullptr, nullptr);
    // conv3: ha -> offset/mask  (A resident; slices 0-3 on y=0, 4-6 on y=1)
    tconv_kernel<1, 448, 1, 8, 4><<<dim3(NTILE, 2, BATCH), 512, TCM_SMEM>>>(
        ahi, alo, (float*)pw3h, (float*)pw3l, ob3, nullptr, nullptr,
        offb, maskb, flow1, flow2);

    int smem = 16 * SSTRIDE * (int)sizeof(float);
    cudaFuncSetAttribute(deform_kernel, cudaFuncAttributeMaxDynamicSharedMemorySize, smem);
    deform_kernel<<<dim3(6, 96, BATCH), 256, smem>>>(xtb, offb, maskb, wdb, bias, out);
}